// round 6
// baseline (speedup 1.0000x reference)
#include <cuda_runtime.h>
#include <math.h>
#include <stdint.h>

// Problem constants
#define NT 365
#define NS 300
#define NH 128
#define NG 32
#define NR 8
#define NROWS (NT*NS)          // 109500
#define KDIM 256
#define NDIM 384               // NH*3
#define MTILE 128
#define NTILES ((NROWS + MTILE - 1)/MTILE)   // 856

// ---------------- scratch (device globals; no allocation in kernel_launch) --------
__device__ float g_Pl[NROWS*NH];         // rain per bucket
__device__ float g_Ev[NROWS*NH];         // evap per bucket
__device__ float g_vm[NROWS*NH];         // melt cap
__device__ float g_QS[NROWS*NH];         // q1+q2+q3
__device__ float g_CS[NROWS*NH];         // q1*cp/10 + q2*cs + q3*cg
__device__ float g_Ps [NROWS];           // snow precip (scalar per row)
__device__ float g_Plb[NROWS];           // P*(1-vf)
__device__ float g_cT[KDIM*NS];          // fcT layer1 static part, TRANSPOSED [k][s]
__device__ float g_cc[NS*NDIM];          // fcCT static part (incl bias)
__device__ float g_gates[NS*6*NH];       // kp,ks,kg,gp,gL,qb
__device__ float g_rg[NS*NH*NR];         // relu(r) * ga  (ga folded into taps)

// =============================== small helpers ====================================
__device__ __forceinline__ float to_tf32(float x) {
    uint32_t u; asm("cvt.rna.tf32.f32 %0, %1;" : "=r"(u) : "f"(x));
    return __uint_as_float(u);
}
__device__ __forceinline__ void mma16n8k8(float* c, const uint32_t* a, const uint32_t* b) {
    asm volatile("mma.sync.aligned.m16n8k8.row.col.f32.tf32.tf32.f32 "
        "{%0,%1,%2,%3}, {%4,%5,%6,%7}, {%8,%9}, {%0,%1,%2,%3};"
        : "+f"(c[0]), "+f"(c[1]), "+f"(c[2]), "+f"(c[3])
        : "r"(a[0]), "r"(a[1]), "r"(a[2]), "r"(a[3]), "r"(b[0]), "r"(b[1]));
}

// ======================= Kernel 1: per-site MLPs (fcW, fcR, statics) ==============
#define SB 6    // sites per block; 300/6 = 50 blocks
__global__ void __launch_bounds__(256) site_kernel(
    const float* __restrict__ xc,
    const float* __restrict__ fcR_w1, const float* __restrict__ fcR_b1,
    const float* __restrict__ fcR_w2, const float* __restrict__ fcR_b2,
    const float* __restrict__ fcW_w1, const float* __restrict__ fcW_b1,
    const float* __restrict__ fcW_w2, const float* __restrict__ fcW_b2,
    const float* __restrict__ fcT_w1, const float* __restrict__ fcT_b1,
    const float* __restrict__ fcCT_w, const float* __restrict__ fcCT_b)
{
    int s0  = blockIdx.x * SB;
    int tid = threadIdx.x;
    __shared__ float sxc[SB][32];
    __shared__ float hW [SB][257];
    __shared__ float hR [SB][257];
    __shared__ float sga[SB][128];

    for (int i = tid; i < SB*32; i += 256)
        sxc[i/32][i%32] = xc[(s0 + i/32)*32 + (i%32)];
    __syncthreads();

    {
        int k = tid;
        float aW[SB], aR[SB], aT[SB];
        #pragma unroll
        for (int s = 0; s < SB; s++) { aW[s]=0.f; aR[s]=0.f; aT[s]=0.f; }
        for (int j = 0; j < 32; j++) {
            float wW = fcW_w1[k*32 + j];
            float wR = fcR_w1[k*32 + j];
            float wT = fcT_w1[k*38 + 6 + j];
            #pragma unroll
            for (int s = 0; s < SB; s++) {
                float xv = sxc[s][j];
                aW[s] += wW*xv; aR[s] += wR*xv; aT[s] += wT*xv;
            }
        }
        float bW = fcW_b1[k], bR = fcR_b1[k], bT = fcT_b1[k];
        #pragma unroll
        for (int s = 0; s < SB; s++) {
            hW[s][k] = tanhf(aW[s] + bW);
            hR[s][k] = tanhf(aR[s] + bR);
            g_cT[k*NS + (s0+s)] = aT[s] + bT;       // transposed [k][s]
        }
    }
    for (int o = tid; o < NDIM; o += 256) {
        float acc[SB];
        float b = fcCT_b[o];
        #pragma unroll
        for (int s = 0; s < SB; s++) acc[s] = b;
        for (int j = 0; j < 32; j++) {
            float w = fcCT_w[o*34 + 2 + j];
            #pragma unroll
            for (int s = 0; s < SB; s++) acc[s] += w * sxc[s][j];
        }
        #pragma unroll
        for (int s = 0; s < SB; s++) g_cc[(s0+s)*NDIM + o] = acc[s];
    }
    __syncthreads();

    for (int o = tid; o < 7*NH; o += 256) {
        float acc[SB];
        float b = fcW_b2[o];
        #pragma unroll
        for (int s = 0; s < SB; s++) acc[s] = b;
        for (int k = 0; k < KDIM; k++) {
            float w = fcW_w2[o*KDIM + k];
            #pragma unroll
            for (int s = 0; s < SB; s++) acc[s] += w * hW[s][k];
        }
        int g = o >> 7, h = o & 127;
        #pragma unroll
        for (int s = 0; s < SB; s++) {
            float a = acc[s];
            if      (g < 4)  g_gates[(s0+s)*6*NH + g*NH + h] = 1.f/(1.f + expf(-a));
            else if (g == 4) g_gates[(s0+s)*6*NH + 4*NH + h] = expf(a)*2.f;
            else if (g == 5) g_gates[(s0+s)*6*NH + 5*NH + h] = fmaxf(a, 0.f);
            else             sga[s][h] = a;
        }
    }
    __syncthreads();

    if (tid < SB) {
        float m = -1e30f;
        for (int h = 0; h < NH; h++) m = fmaxf(m, sga[tid][h]);
        float sum = 0.f;
        for (int h = 0; h < NH; h++) { float e = expf(sga[tid][h] - m); sga[tid][h] = e; sum += e; }
        float inv = 1.f / sum;
        for (int h = 0; h < NH; h++) sga[tid][h] *= inv;
    }
    __syncthreads();

    for (int o = tid; o < NH*NR; o += 256) {
        float acc[SB];
        float b = fcR_b2[o];
        #pragma unroll
        for (int s = 0; s < SB; s++) acc[s] = b;
        for (int k = 0; k < KDIM; k++) {
            float w = fcR_w2[o*KDIM + k];
            #pragma unroll
            for (int s = 0; s < SB; s++) acc[s] += w * hR[s][k];
        }
        int h = o >> 3;
        #pragma unroll
        for (int s = 0; s < SB; s++)
            g_rg[(s0+s)*NH*NR + o] = fmaxf(acc[s], 0.f) * sga[s][h];
    }
}

// ============================ Kernel 2a: snow split ===============================
__global__ void __launch_bounds__(256) snow_kernel(const float* __restrict__ x)
{
    int rm = blockIdx.x*256 + threadIdx.x;
    if (rm >= NROWS) return;
    const float* xr = x + (size_t)rm*6;
    float P = xr[0], T1 = xr[2], T2 = xr[3];
    float d = T2 - T1;
    float ratio = (T1 + T2) / (d == 0.f ? 1.f : d);
    ratio = fminf(fmaxf(ratio, -1.f), 1.f);
    float vf = acosf(ratio) / 3.1415f;
    if (T1 >= 0.f) vf = 0.f;
    else if (T2 <= 0.f) vf = 1.f;
    g_Ps [rm] = P * vf;
    g_Plb[rm] = P * (1.f - vf);
}

// ====== Kernel 2b: fused fcT (layer-1 tanh + 3xTF32 mma.sync GEMM + epilogue) =====
// CTA tile: M=128, N=64.  8 warps of 32x32.  BK=32, K=256 (8 chunks).
// SMEM (floats): AH[32][136], AL[32][136], BH[32][72], BL[32][72]
#define SA 136
#define SBN 72
#define AOFF_L (32*SA)
#define BOFF_H (2*32*SA)
#define BOFF_L (BOFF_H + 32*SBN)
#define SM_FLOATS (BOFF_L + 32*SBN)
#define SM_BYTES  (SM_FLOATS*4)          // 53248

__global__ void __launch_bounds__(256)
fct_mma_kernel(const float* __restrict__ x,
               const float* __restrict__ fcT_w1,
               const float* __restrict__ W2,
               const float* __restrict__ b2)
{
    extern __shared__ float sm[];
    int tid  = threadIdx.x;
    int lane = tid & 31, wid = tid >> 5;
    int wm = (wid & 3) * 32;            // warp m-offset within 128
    int wn = (wid >> 2) * 32;           // warp n-offset within 64
    int grp = lane >> 2, tig = lane & 3;
    int rowBase = blockIdx.x * MTILE;
    int nBase   = blockIdx.y * 64;
    int g       = blockIdx.y >> 1;      // activation group (N group of 128)

    float acc[2][4][4];
    #pragma unroll
    for (int mt = 0; mt < 2; mt++)
        #pragma unroll
        for (int nt = 0; nt < 4; nt++)
            #pragma unroll
            for (int q = 0; q < 4; q++) acc[mt][nt][q] = 0.f;

    // per-thread fixed row for A fill
    int am = tid & 127;              // m index
    int rmA = rowBase + am;
    int sA = rmA % NS;
    float xr[6];
    if (rmA < NROWS) {
        #pragma unroll
        for (int j = 0; j < 6; j++) xr[j] = x[(size_t)rmA*6 + j];
    } else {
        #pragma unroll
        for (int j = 0; j < 6; j++) xr[j] = 0.f;
    }
    int kkBase = tid >> 7;           // 0 or 1

    for (int chunk = 0; chunk < 8; chunk++) {
        int k0 = chunk * 32;
        // ---- fill A: layer-1 fused (tanh), split hi/lo ----
        #pragma unroll
        for (int i = 0; i < 16; i++) {
            int kk = kkBase + 2*i;           // 0..31
            int k  = k0 + kk;
            float a = 0.f;
            if (rmA < NROWS) {
                const float* w = fcT_w1 + k*38;
                float t = g_cT[k*NS + sA];
                #pragma unroll
                for (int j = 0; j < 6; j++) t += w[j]*xr[j];
                a = tanhf(t);
            }
            float ah = __uint_as_float(__float_as_uint(a) & 0xFFFFE000u);
            float al = to_tf32(a - ah);
            sm[kk*SA + am]          = ah;
            sm[AOFF_L + kk*SA + am] = al;
        }
        // ---- fill B: W2 chunk, split hi/lo ----
        #pragma unroll
        for (int i = 0; i < 8; i++) {
            int idx = tid + i*256;
            int n = idx >> 5, kk = idx & 31;
            float b = W2[(size_t)(nBase + n)*KDIM + k0 + kk];
            float bh = __uint_as_float(__float_as_uint(b) & 0xFFFFE000u);
            float bl = to_tf32(b - bh);
            sm[BOFF_H + kk*SBN + n] = bh;
            sm[BOFF_L + kk*SBN + n] = bl;
        }
        __syncthreads();

        // ---- 4 k8-steps of mma ----
        #pragma unroll
        for (int ks = 0; ks < 4; ks++) {
            int k = ks*8;
            uint32_t ah[2][4], al[2][4], bh[4][2], bl[4][2];
            #pragma unroll
            for (int mt = 0; mt < 2; mt++) {
                int m0 = wm + mt*16 + grp;
                int r0 = (k + tig)*SA, r4 = (k + tig + 4)*SA;
                ah[mt][0] = __float_as_uint(sm[r0 + m0]);
                ah[mt][1] = __float_as_uint(sm[r0 + m0 + 8]);
                ah[mt][2] = __float_as_uint(sm[r4 + m0]);
                ah[mt][3] = __float_as_uint(sm[r4 + m0 + 8]);
                al[mt][0] = __float_as_uint(sm[AOFF_L + r0 + m0]);
                al[mt][1] = __float_as_uint(sm[AOFF_L + r0 + m0 + 8]);
                al[mt][2] = __float_as_uint(sm[AOFF_L + r4 + m0]);
                al[mt][3] = __float_as_uint(sm[AOFF_L + r4 + m0 + 8]);
            }
            #pragma unroll
            for (int nt = 0; nt < 4; nt++) {
                int n0 = wn + nt*8 + grp;
                int r0 = (k + tig)*SBN, r4 = (k + tig + 4)*SBN;
                bh[nt][0] = __float_as_uint(sm[BOFF_H + r0 + n0]);
                bh[nt][1] = __float_as_uint(sm[BOFF_H + r4 + n0]);
                bl[nt][0] = __float_as_uint(sm[BOFF_L + r0 + n0]);
                bl[nt][1] = __float_as_uint(sm[BOFF_L + r4 + n0]);
            }
            #pragma unroll
            for (int mt = 0; mt < 2; mt++)
                #pragma unroll
                for (int nt = 0; nt < 4; nt++) {
                    mma16n8k8(acc[mt][nt], ah[mt], bh[nt]);
                    mma16n8k8(acc[mt][nt], ah[mt], bl[nt]);
                    mma16n8k8(acc[mt][nt], al[mt], bh[nt]);
                }
        }
        __syncthreads();
    }

    // ---- epilogue: bias + activation + store ----
    int nHalf = (blockIdx.y & 1)*64;
    #pragma unroll
    for (int mt = 0; mt < 2; mt++) {
        #pragma unroll
        for (int half = 0; half < 2; half++) {
            int rm = rowBase + wm + mt*16 + grp + half*8;
            if (rm >= NROWS) continue;
            float plb = 0.f, Esc = 0.f;
            if      (g == 0) plb = g_Plb[rm];
            else if (g == 1) Esc = x[(size_t)rm*6 + 1];
            #pragma unroll
            for (int nt = 0; nt < 4; nt++) {
                int colg = nHalf + wn + nt*8 + 2*tig;   // column within NH group
                float v0 = acc[mt][nt][half*2 + 0] + __ldg(&b2[g*128 + colg]);
                float v1 = acc[mt][nt][half*2 + 1] + __ldg(&b2[g*128 + colg + 1]);
                float2 o;
                if (g == 0) {
                    o.x = plb * fminf(fmaxf(v0*(1.f/3.f) + 0.5f, 0.f), 1.f);
                    o.y = plb * fminf(fmaxf(v1*(1.f/3.f) + 0.5f, 0.f), 1.f);
                    *(float2*)&g_Pl[(size_t)rm*NH + colg] = o;
                } else if (g == 1) {
                    o.x = Esc * fmaxf(v0, 0.f) * 2.f;
                    o.y = Esc * fmaxf(v1, 0.f) * 2.f;
                    *(float2*)&g_Ev[(size_t)rm*NH + colg] = o;
                } else {
                    o.x = expf(v0);
                    o.y = expf(v1);
                    *(float2*)&g_vm[(size_t)rm*NH + colg] = o;
                }
            }
        }
    }
}

// ========================= Kernel 3: sequential bucket scan =======================
// 4-deep software-pipelined prefetch (12 outstanding loads/thread).
__global__ void __launch_bounds__(128) scan_kernel(
    const float* __restrict__ x, const float* __restrict__ fcCT_w)
{
    int s = blockIdx.x, h = threadIdx.x;
    const float* G = g_gates + s*6*NH;
    float kp = G[0*NH+h], ksv = G[1*NH+h], kg = G[2*NH+h];
    float gp = G[3*NH+h], gL  = G[4*NH+h], qb = G[5*NH+h];
    float cc0 = g_cc[s*NDIM + h];
    float cc1 = g_cc[s*NDIM + NH + h];
    float cc2 = g_cc[s*NDIM + 2*NH + h];
    float wp1 = fcCT_w[(h)*34 + 0],      wp2 = fcCT_w[(h)*34 + 1];
    float ws1 = fcCT_w[(NH+h)*34 + 0],   ws2 = fcCT_w[(NH+h)*34 + 1];
    float wg1 = fcCT_w[(2*NH+h)*34 + 0], wg2 = fcCT_w[(2*NH+h)*34 + 1];

    float Sf = 0.f, Ss = 0.f, Sg = 0.f;
    const int base = s*NH + h;
    float pl[4], ev[4], vm[4];
    #pragma unroll
    for (int j = 0; j < 4; j++) {
        int ix = j*NS*NH + base;
        pl[j] = g_Pl[ix]; ev[j] = g_Ev[ix]; vm[j] = g_vm[ix];
    }

    for (int t0 = 0; t0 < NT-1; t0 += 4) {      // t = 0..363
        #pragma unroll
        for (int j = 0; j < 4; j++) {
            int t  = t0 + j;
            int rm = t*NS + s;
            float Psv = g_Ps[rm];
            float T1  = x[(size_t)rm*6 + 2];
            float T2  = x[(size_t)rm*6 + 3];

            float a  = Sf + Psv;
            float qf = fminf(a, vm[j]);
            Sf = fmaxf(a - vm[j], 0.f);
            float H  = fmaxf(Ss + pl[j] + qf - ev[j], 0.f);
            float qp = fmaxf(kp*(H - gL), 0.f);
            float qs = ksv * fminf(H, gL);
            Ss = H - qp - qs;
            float qso = qs*(1.f - gp);
            float qsg = qs*gp;
            float sg2 = Sg + qsg;
            float qg  = kg*sg2 + qb;
            Sg = (1.f - kg)*sg2 - qb;

            float cp = expf(cc0 + T1*wp1 + T2*wp2);
            float cs = expf(cc1 + T1*ws1 + T2*ws2);
            float cg = expf(cc2 + T1*wg1 + T2*wg2);

            int idx = t*NS*NH + base;
            g_QS[idx] = qp + qso + qg;
            g_CS[idx] = qp*cp*0.1f + qso*cs + qg*cg;

            int tn = t + 4;
            if (tn < NT) {
                int ix = tn*NS*NH + base;
                pl[j] = g_Pl[ix]; ev[j] = g_Ev[ix]; vm[j] = g_vm[ix];
            }
        }
    }
    // tail t = 364 (inputs in slot 0)
    {
        int t  = NT-1;
        int rm = t*NS + s;
        float Psv = g_Ps[rm];
        float T1  = x[(size_t)rm*6 + 2];
        float T2  = x[(size_t)rm*6 + 3];
        float a  = Sf + Psv;
        float qf = fminf(a, vm[0]);
        Sf = fmaxf(a - vm[0], 0.f);
        float H  = fmaxf(Ss + pl[0] + qf - ev[0], 0.f);
        float qp = fmaxf(kp*(H - gL), 0.f);
        float qs = ksv * fminf(H, gL);
        Ss = H - qp - qs;
        float qso = qs*(1.f - gp);
        float qsg = qs*gp;
        float sg2 = Sg + qsg;
        float qg  = kg*sg2 + qb;
        float cp = expf(cc0 + T1*wp1 + T2*wp2);
        float cs = expf(cc1 + T1*ws1 + T2*ws2);
        float cg = expf(cc2 + T1*wg1 + T2*wg2);
        int idx = t*NS*NH + base;
        g_QS[idx] = qp + qso + qg;
        g_CS[idx] = qp*cp*0.1f + qso*cs + qg*cg;
    }
}

// ================== Kernel 4: routed conv + ga-reduction + outputs ================
#define TT 73   // 365 = 5*73
__global__ void __launch_bounds__(128) conv_kernel(float* __restrict__ out)
{
    int chunk = blockIdx.x, s = blockIdx.y, h = threadIdx.x;
    int t0 = chunk * TT;

    float rg[NR];
    #pragma unroll
    for (int i = 0; i < NR; i++) rg[i] = g_rg[s*NH*NR + h*NR + i];

    float qh[NR], ch[NR];
    #pragma unroll
    for (int j = 0; j < NR-1; j++) {
        int t = t0 - 1 - j;
        if (t >= 0) {
            int idx = t*NS*NH + s*NH + h;
            qh[j] = g_QS[idx]; ch[j] = g_CS[idx];
        } else { qh[j] = 0.f; ch[j] = 0.f; }
    }
    qh[NR-1] = 0.f; ch[NR-1] = 0.f;

    __shared__ float sQ[4], sC[4];
    int lane = h & 31, warp = h >> 5;

    for (int tt = 0; tt < TT; tt++) {
        int t = t0 + tt;
        #pragma unroll
        for (int i = NR-1; i >= 1; i--) { qh[i] = qh[i-1]; ch[i] = ch[i-1]; }
        int idx = t*NS*NH + s*NH + h;
        qh[0] = g_QS[idx]; ch[0] = g_CS[idx];

        float pq = 0.f, pc = 0.f;
        #pragma unroll
        for (int i = 0; i < NR; i++) { pq += qh[i]*rg[i]; pc += ch[i]*rg[i]; }

        #pragma unroll
        for (int o = 16; o; o >>= 1) {
            pq += __shfl_down_sync(0xffffffffu, pq, o);
            pc += __shfl_down_sync(0xffffffffu, pc, o);
        }
        if (lane == 0) { sQ[warp] = pq; sC[warp] = pc; }
        __syncthreads();
        if (h == 0) {
            float q = sQ[0]+sQ[1]+sQ[2]+sQ[3];
            float c = sC[0]+sC[1]+sC[2]+sC[3];
            out[t*NS + s]          = q;
            out[NROWS + t*NS + s]  = c / q;
        }
        __syncthreads();
    }
}

// ==================================== launch ======================================
extern "C" void kernel_launch(void* const* d_in, const int* in_sizes, int n_in,
                              void* d_out, int out_size)
{
    const float* x       = (const float*)d_in[0];
    const float* xc      = (const float*)d_in[1];
    const float* fcR_w1  = (const float*)d_in[2];
    const float* fcR_b1  = (const float*)d_in[3];
    const float* fcR_w2  = (const float*)d_in[4];
    const float* fcR_b2  = (const float*)d_in[5];
    const float* fcW_w1  = (const float*)d_in[6];
    const float* fcW_b1  = (const float*)d_in[7];
    const float* fcW_w2  = (const float*)d_in[8];
    const float* fcW_b2  = (const float*)d_in[9];
    const float* fcT_w1  = (const float*)d_in[10];
    const float* fcT_b1  = (const float*)d_in[11];
    const float* fcT_w2  = (const float*)d_in[12];
    const float* fcT_b2  = (const float*)d_in[13];
    const float* fcCT_w  = (const float*)d_in[14];
    const float* fcCT_b  = (const float*)d_in[15];
    float* out = (float*)d_out;

    // Idempotent, not a stream op (not captured); called every time — no static guards.
    cudaFuncSetAttribute(fct_mma_kernel, cudaFuncAttributeMaxDynamicSharedMemorySize, SM_BYTES);

    site_kernel<<<NS/SB, 256>>>(xc, fcR_w1, fcR_b1, fcR_w2, fcR_b2,
                                fcW_w1, fcW_b1, fcW_w2, fcW_b2,
                                fcT_w1, fcT_b1, fcCT_w, fcCT_b);
    snow_kernel<<<(NROWS + 255)/256, 256>>>(x);
    dim3 gg(NTILES, 6);
    fct_mma_kernel<<<gg, 256, SM_BYTES>>>(x, fcT_w1, fcT_w2, fcT_b2);
    scan_kernel<<<NS, 128>>>(x, fcCT_w);
    dim3 gc(NT/TT, NS);
    conv_kernel<<<gc, 128>>>(out);
}

// round 8
// speedup vs baseline: 1.2109x; 1.2109x over previous
#include <cuda_runtime.h>
#include <math.h>
#include <stdint.h>

// Problem constants
#define NT 365
#define NS 300
#define NH 128
#define NG 32
#define NR 8
#define NROWS (NT*NS)          // 109500
#define KDIM 256
#define NDIM 384               // NH*3
#define MTILE 128
#define NTILES ((NROWS + MTILE - 1)/MTILE)   // 856

// ---------------- scratch (device globals; no allocation in kernel_launch) --------
__device__ float g_H [NROWS*KDIM];       // tanh hidden of fcT, [row][k]
__device__ float g_Pl[NROWS*NH];         // rain per bucket
__device__ float g_Ev[NROWS*NH];         // evap per bucket
__device__ float g_vm[NROWS*NH];         // melt cap
__device__ float g_QS[NROWS*NH];         // q1+q2+q3
__device__ float g_CS[NROWS*NH];         // q1*cp/10 + q2*cs + q3*cg
__device__ float g_Ps [NROWS];           // snow precip (scalar per row)
__device__ float g_Plb[NROWS];           // P*(1-vf)
__device__ float g_cT[NS*KDIM];          // fcT layer1 static part [s][k] (incl b1)
__device__ float g_cc[NS*NDIM];          // fcCT static part (incl bias)
__device__ float g_gates[NS*6*NH];       // kp,ks,kg,gp,gL,qb
__device__ float g_rg[NS*NH*NR];         // relu(r) * ga  (ga folded into taps)

// =============================== small helpers ====================================
__device__ __forceinline__ float to_tf32(float x) {
    uint32_t u; asm("cvt.rna.tf32.f32 %0, %1;" : "=r"(u) : "f"(x));
    return __uint_as_float(u);
}
__device__ __forceinline__ void mma16n8k8(float* c, const uint32_t* a, const uint32_t* b) {
    asm volatile("mma.sync.aligned.m16n8k8.row.col.f32.tf32.tf32.f32 "
        "{%0,%1,%2,%3}, {%4,%5,%6,%7}, {%8,%9}, {%0,%1,%2,%3};"
        : "+f"(c[0]), "+f"(c[1]), "+f"(c[2]), "+f"(c[3])
        : "r"(a[0]), "r"(a[1]), "r"(a[2]), "r"(a[3]), "r"(b[0]), "r"(b[1]));
}

// ======================= Kernel 1: per-site MLPs (fcW, fcR, statics) ==============
#define SB 6    // sites per block; 300/6 = 50 blocks
__global__ void __launch_bounds__(256) site_kernel(
    const float* __restrict__ xc,
    const float* __restrict__ fcR_w1, const float* __restrict__ fcR_b1,
    const float* __restrict__ fcR_w2, const float* __restrict__ fcR_b2,
    const float* __restrict__ fcW_w1, const float* __restrict__ fcW_b1,
    const float* __restrict__ fcW_w2, const float* __restrict__ fcW_b2,
    const float* __restrict__ fcT_w1, const float* __restrict__ fcT_b1,
    const float* __restrict__ fcCT_w, const float* __restrict__ fcCT_b)
{
    int s0  = blockIdx.x * SB;
    int tid = threadIdx.x;
    __shared__ float sxc[SB][32];
    __shared__ float hW [SB][257];
    __shared__ float hR [SB][257];
    __shared__ float sga[SB][128];

    for (int i = tid; i < SB*32; i += 256)
        sxc[i/32][i%32] = xc[(s0 + i/32)*32 + (i%32)];
    __syncthreads();

    {
        int k = tid;
        float aW[SB], aR[SB], aT[SB];
        #pragma unroll
        for (int s = 0; s < SB; s++) { aW[s]=0.f; aR[s]=0.f; aT[s]=0.f; }
        for (int j = 0; j < 32; j++) {
            float wW = fcW_w1[k*32 + j];
            float wR = fcR_w1[k*32 + j];
            float wT = fcT_w1[k*38 + 6 + j];
            #pragma unroll
            for (int s = 0; s < SB; s++) {
                float xv = sxc[s][j];
                aW[s] += wW*xv; aR[s] += wR*xv; aT[s] += wT*xv;
            }
        }
        float bW = fcW_b1[k], bR = fcR_b1[k], bT = fcT_b1[k];
        #pragma unroll
        for (int s = 0; s < SB; s++) {
            hW[s][k] = tanhf(aW[s] + bW);
            hR[s][k] = tanhf(aR[s] + bR);
            g_cT[(s0+s)*KDIM + k] = aT[s] + bT;
        }
    }
    for (int o = tid; o < NDIM; o += 256) {
        float acc[SB];
        float b = fcCT_b[o];
        #pragma unroll
        for (int s = 0; s < SB; s++) acc[s] = b;
        for (int j = 0; j < 32; j++) {
            float w = fcCT_w[o*34 + 2 + j];
            #pragma unroll
            for (int s = 0; s < SB; s++) acc[s] += w * sxc[s][j];
        }
        #pragma unroll
        for (int s = 0; s < SB; s++) g_cc[(s0+s)*NDIM + o] = acc[s];
    }
    __syncthreads();

    for (int o = tid; o < 7*NH; o += 256) {
        float acc[SB];
        float b = fcW_b2[o];
        #pragma unroll
        for (int s = 0; s < SB; s++) acc[s] = b;
        for (int k = 0; k < KDIM; k++) {
            float w = fcW_w2[o*KDIM + k];
            #pragma unroll
            for (int s = 0; s < SB; s++) acc[s] += w * hW[s][k];
        }
        int g = o >> 7, h = o & 127;
        #pragma unroll
        for (int s = 0; s < SB; s++) {
            float a = acc[s];
            if      (g < 4)  g_gates[(s0+s)*6*NH + g*NH + h] = 1.f/(1.f + expf(-a));
            else if (g == 4) g_gates[(s0+s)*6*NH + 4*NH + h] = expf(a)*2.f;
            else if (g == 5) g_gates[(s0+s)*6*NH + 5*NH + h] = fmaxf(a, 0.f);
            else             sga[s][h] = a;
        }
    }
    __syncthreads();

    if (tid < SB) {
        float m = -1e30f;
        for (int h = 0; h < NH; h++) m = fmaxf(m, sga[tid][h]);
        float sum = 0.f;
        for (int h = 0; h < NH; h++) { float e = expf(sga[tid][h] - m); sga[tid][h] = e; sum += e; }
        float inv = 1.f / sum;
        for (int h = 0; h < NH; h++) sga[tid][h] *= inv;
    }
    __syncthreads();

    for (int o = tid; o < NH*NR; o += 256) {
        float acc[SB];
        float b = fcR_b2[o];
        #pragma unroll
        for (int s = 0; s < SB; s++) acc[s] = b;
        for (int k = 0; k < KDIM; k++) {
            float w = fcR_w2[o*KDIM + k];
            #pragma unroll
            for (int s = 0; s < SB; s++) acc[s] += w * hR[s][k];
        }
        int h = o >> 3;
        #pragma unroll
        for (int s = 0; s < SB; s++)
            g_rg[(s0+s)*NH*NR + o] = fmaxf(acc[s], 0.f) * sga[s][h];
    }
}

// =================== Kernel 2a: fcT layer-1 (tanh) ONCE + snow split ==============
__global__ void __launch_bounds__(256) hidden_kernel(
    const float* __restrict__ x, const float* __restrict__ fcT_w1)
{
    int rm = blockIdx.x;             // row = t*NS + s
    int k  = threadIdx.x;
    int s  = rm % NS;
    const float* xr = x + (size_t)rm*6;
    float acc = g_cT[s*KDIM + k];
    #pragma unroll
    for (int j = 0; j < 6; j++) acc += fcT_w1[k*38 + j] * xr[j];
    g_H[(size_t)rm*KDIM + k] = tanhf(acc);

    if (k == 0) {
        float P = xr[0], T1 = xr[2], T2 = xr[3];
        float d = T2 - T1;
        float ratio = (T1 + T2) / (d == 0.f ? 1.f : d);
        ratio = fminf(fmaxf(ratio, -1.f), 1.f);
        float vf = acosf(ratio) / 3.1415f;
        if (T1 >= 0.f) vf = 0.f;
        else if (T2 <= 0.f) vf = 1.f;
        g_Ps [rm] = P * vf;
        g_Plb[rm] = P * (1.f - vf);
    }
}

// ========= Kernel 2b: fcT layer-2 (3xTF32 mma.sync GEMM + fused epilogue) =========
// CTA tile: M=128, N=64.  8 warps of 32x32.  BK=32, K=256 (8 chunks).
// grid = (6 ngroups, 856 row tiles): x fastest -> 6 CTAs sharing an A tile are
// co-resident -> A rereads hit L2.
// SMEM (floats): AH[32][136], AL[32][136], BH[32][72], BL[32][72]
#define SA 136
#define SBN 72
#define AOFF_L (32*SA)
#define BOFF_H (2*32*SA)
#define BOFF_L (BOFF_H + 32*SBN)
#define SM_FLOATS (BOFF_L + 32*SBN)
#define SM_BYTES  (SM_FLOATS*4)          // 53248

__global__ void __launch_bounds__(256)
fct_mma_kernel(const float* __restrict__ x,
               const float* __restrict__ W2,
               const float* __restrict__ b2)
{
    extern __shared__ float sm[];
    int tid  = threadIdx.x;
    int lane = tid & 31, wid = tid >> 5;
    int wm = (wid & 3) * 32;            // warp m-offset within 128
    int wn = (wid >> 2) * 32;           // warp n-offset within 64
    int grp = lane >> 2, tig = lane & 3;
    int rowBase = blockIdx.y * MTILE;
    int nBase   = blockIdx.x * 64;
    int g       = blockIdx.x >> 1;      // activation group (N group of 128)

    float acc[2][4][4];
    #pragma unroll
    for (int mt = 0; mt < 2; mt++)
        #pragma unroll
        for (int nt = 0; nt < 4; nt++)
            #pragma unroll
            for (int q = 0; q < 4; q++) acc[mt][nt][q] = 0.f;

    int ar   = tid >> 1;          // A-fill row 0..127
    int ahal = tid & 1;           // which 16-float half of the BK=32 slice
    int rmA  = rowBase + ar;
    bool aok = rmA < NROWS;

    for (int chunk = 0; chunk < 8; chunk++) {
        int k0 = chunk * 32;
        // ---- fill A: load H from gmem, split hi/lo ----
        #pragma unroll
        for (int i = 0; i < 4; i++) {
            float4 v = make_float4(0.f,0.f,0.f,0.f);
            if (aok) v = *(const float4*)&g_H[(size_t)rmA*KDIM + k0 + ahal*16 + i*4];
            const float* vp = (const float*)&v;
            #pragma unroll
            for (int u = 0; u < 4; u++) {
                int kk = ahal*16 + i*4 + u;
                float a  = vp[u];
                float ah = __uint_as_float(__float_as_uint(a) & 0xFFFFE000u);
                float al = to_tf32(a - ah);
                sm[kk*SA + ar]          = ah;
                sm[AOFF_L + kk*SA + ar] = al;
            }
        }
        // ---- fill B: W2 chunk, split hi/lo ----
        #pragma unroll
        for (int i = 0; i < 8; i++) {
            int idx = tid + i*256;
            int n = idx >> 5, kk = idx & 31;
            float b = W2[(size_t)(nBase + n)*KDIM + k0 + kk];
            float bh = __uint_as_float(__float_as_uint(b) & 0xFFFFE000u);
            float bl = to_tf32(b - bh);
            sm[BOFF_H + kk*SBN + n] = bh;
            sm[BOFF_L + kk*SBN + n] = bl;
        }
        __syncthreads();

        // ---- 4 k8-steps of mma ----
        #pragma unroll
        for (int ks = 0; ks < 4; ks++) {
            int k = ks*8;
            uint32_t ah[2][4], al[2][4], bh[4][2], bl[4][2];
            #pragma unroll
            for (int mt = 0; mt < 2; mt++) {
                int m0 = wm + mt*16 + grp;
                int r0 = (k + tig)*SA, r4 = (k + tig + 4)*SA;
                ah[mt][0] = __float_as_uint(sm[r0 + m0]);
                ah[mt][1] = __float_as_uint(sm[r0 + m0 + 8]);
                ah[mt][2] = __float_as_uint(sm[r4 + m0]);
                ah[mt][3] = __float_as_uint(sm[r4 + m0 + 8]);
                al[mt][0] = __float_as_uint(sm[AOFF_L + r0 + m0]);
                al[mt][1] = __float_as_uint(sm[AOFF_L + r0 + m0 + 8]);
                al[mt][2] = __float_as_uint(sm[AOFF_L + r4 + m0]);
                al[mt][3] = __float_as_uint(sm[AOFF_L + r4 + m0 + 8]);
            }
            #pragma unroll
            for (int nt = 0; nt < 4; nt++) {
                int n0 = wn + nt*8 + grp;
                int r0 = (k + tig)*SBN, r4 = (k + tig + 4)*SBN;
                bh[nt][0] = __float_as_uint(sm[BOFF_H + r0 + n0]);
                bh[nt][1] = __float_as_uint(sm[BOFF_H + r4 + n0]);
                bl[nt][0] = __float_as_uint(sm[BOFF_L + r0 + n0]);
                bl[nt][1] = __float_as_uint(sm[BOFF_L + r4 + n0]);
            }
            #pragma unroll
            for (int mt = 0; mt < 2; mt++)
                #pragma unroll
                for (int nt = 0; nt < 4; nt++) {
                    mma16n8k8(acc[mt][nt], ah[mt], bh[nt]);
                    mma16n8k8(acc[mt][nt], ah[mt], bl[nt]);
                    mma16n8k8(acc[mt][nt], al[mt], bh[nt]);
                }
        }
        __syncthreads();
    }

    // ---- epilogue: bias + activation + store ----
    int nHalf = (blockIdx.x & 1)*64;
    #pragma unroll
    for (int mt = 0; mt < 2; mt++) {
        #pragma unroll
        for (int half = 0; half < 2; half++) {
            int rm = rowBase + wm + mt*16 + grp + half*8;
            if (rm >= NROWS) continue;
            float plb = 0.f, Esc = 0.f;
            if      (g == 0) plb = g_Plb[rm];
            else if (g == 1) Esc = x[(size_t)rm*6 + 1];
            #pragma unroll
            for (int nt = 0; nt < 4; nt++) {
                int colg = nHalf + wn + nt*8 + 2*tig;   // column within NH group
                float v0 = acc[mt][nt][half*2 + 0] + __ldg(&b2[g*128 + colg]);
                float v1 = acc[mt][nt][half*2 + 1] + __ldg(&b2[g*128 + colg + 1]);
                float2 o;
                if (g == 0) {
                    o.x = plb * fminf(fmaxf(v0*(1.f/3.f) + 0.5f, 0.f), 1.f);
                    o.y = plb * fminf(fmaxf(v1*(1.f/3.f) + 0.5f, 0.f), 1.f);
                    *(float2*)&g_Pl[(size_t)rm*NH + colg] = o;
                } else if (g == 1) {
                    o.x = Esc * fmaxf(v0, 0.f) * 2.f;
                    o.y = Esc * fmaxf(v1, 0.f) * 2.f;
                    *(float2*)&g_Ev[(size_t)rm*NH + colg] = o;
                } else {
                    o.x = expf(v0);
                    o.y = expf(v1);
                    *(float2*)&g_vm[(size_t)rm*NH + colg] = o;
                }
            }
        }
    }
}

// ========================= Kernel 3: sequential bucket scan =======================
// 8-deep software-pipelined prefetch (24 outstanding loads/thread).
#define PD 8
__global__ void __launch_bounds__(128) scan_kernel(
    const float* __restrict__ x, const float* __restrict__ fcCT_w)
{
    int s = blockIdx.x, h = threadIdx.x;
    const float* G = g_gates + s*6*NH;
    float kp = G[0*NH+h], ksv = G[1*NH+h], kg = G[2*NH+h];
    float gp = G[3*NH+h], gL  = G[4*NH+h], qb = G[5*NH+h];
    float cc0 = g_cc[s*NDIM + h];
    float cc1 = g_cc[s*NDIM + NH + h];
    float cc2 = g_cc[s*NDIM + 2*NH + h];
    float wp1 = fcCT_w[(h)*34 + 0],      wp2 = fcCT_w[(h)*34 + 1];
    float ws1 = fcCT_w[(NH+h)*34 + 0],   ws2 = fcCT_w[(NH+h)*34 + 1];
    float wg1 = fcCT_w[(2*NH+h)*34 + 0], wg2 = fcCT_w[(2*NH+h)*34 + 1];

    float Sf = 0.f, Ss = 0.f, Sg = 0.f;
    const int base = s*NH + h;
    float pl[PD], ev[PD], vm[PD];
    #pragma unroll
    for (int j = 0; j < PD; j++) {
        int ix = j*NS*NH + base;
        pl[j] = g_Pl[ix]; ev[j] = g_Ev[ix]; vm[j] = g_vm[ix];
    }

    const int TMAIN = ((NT - PD) / PD) * PD + PD;   // 360: main covers t=0..359
    for (int t0 = 0; t0 < TMAIN; t0 += PD) {
        #pragma unroll
        for (int j = 0; j < PD; j++) {
            int t  = t0 + j;
            int rm = t*NS + s;
            float Psv = g_Ps[rm];
            float T1  = x[(size_t)rm*6 + 2];
            float T2  = x[(size_t)rm*6 + 3];

            float a  = Sf + Psv;
            float qf = fminf(a, vm[j]);
            Sf = fmaxf(a - vm[j], 0.f);
            float H  = fmaxf(Ss + pl[j] + qf - ev[j], 0.f);
            float qp = fmaxf(kp*(H - gL), 0.f);
            float qs = ksv * fminf(H, gL);
            Ss = H - qp - qs;
            float qso = qs*(1.f - gp);
            float qsg = qs*gp;
            float sg2 = Sg + qsg;
            float qg  = kg*sg2 + qb;
            Sg = (1.f - kg)*sg2 - qb;

            float cp = expf(cc0 + T1*wp1 + T2*wp2);
            float cs = expf(cc1 + T1*ws1 + T2*ws2);
            float cg = expf(cc2 + T1*wg1 + T2*wg2);

            int idx = t*NS*NH + base;
            g_QS[idx] = qp + qso + qg;
            g_CS[idx] = qp*cp*0.1f + qso*cs + qg*cg;

            int tn = t + PD;
            if (tn < NT) {
                int ix = tn*NS*NH + base;
                pl[j] = g_Pl[ix]; ev[j] = g_Ev[ix]; vm[j] = g_vm[ix];
            }
        }
    }
    // tail t = 360..364 in slots 0..4
    for (int j = 0; j < NT - TMAIN; j++) {
        int t  = TMAIN + j;
        int rm = t*NS + s;
        float Psv = g_Ps[rm];
        float T1  = x[(size_t)rm*6 + 2];
        float T2  = x[(size_t)rm*6 + 3];
        float a  = Sf + Psv;
        float qf = fminf(a, vm[j]);
        Sf = fmaxf(a - vm[j], 0.f);
        float H  = fmaxf(Ss + pl[j] + qf - ev[j], 0.f);
        float qp = fmaxf(kp*(H - gL), 0.f);
        float qs = ksv * fminf(H, gL);
        Ss = H - qp - qs;
        float qso = qs*(1.f - gp);
        float qsg = qs*gp;
        float sg2 = Sg + qsg;
        float qg  = kg*sg2 + qb;
        Sg = (1.f - kg)*sg2 - qb;
        float cp = expf(cc0 + T1*wp1 + T2*wp2);
        float cs = expf(cc1 + T1*ws1 + T2*ws2);
        float cg = expf(cc2 + T1*wg1 + T2*wg2);
        int idx = t*NS*NH + base;
        g_QS[idx] = qp + qso + qg;
        g_CS[idx] = qp*cp*0.1f + qso*cs + qg*cg;
    }
}

// ================== Kernel 4: routed conv + ga-reduction + outputs ================
#define TT 73   // 365 = 5*73
__global__ void __launch_bounds__(128) conv_kernel(float* __restrict__ out)
{
    int chunk = blockIdx.x, s = blockIdx.y, h = threadIdx.x;
    int t0 = chunk * TT;

    float rg[NR];
    #pragma unroll
    for (int i = 0; i < NR; i++) rg[i] = g_rg[s*NH*NR + h*NR + i];

    float qh[NR], ch[NR];
    #pragma unroll
    for (int j = 0; j < NR-1; j++) {
        int t = t0 - 1 - j;
        if (t >= 0) {
            int idx = t*NS*NH + s*NH + h;
            qh[j] = g_QS[idx]; ch[j] = g_CS[idx];
        } else { qh[j] = 0.f; ch[j] = 0.f; }
    }
    qh[NR-1] = 0.f; ch[NR-1] = 0.f;

    __shared__ float sQ[4], sC[4];
    int lane = h & 31, warp = h >> 5;

    for (int tt = 0; tt < TT; tt++) {
        int t = t0 + tt;
        #pragma unroll
        for (int i = NR-1; i >= 1; i--) { qh[i] = qh[i-1]; ch[i] = ch[i-1]; }
        int idx = t*NS*NH + s*NH + h;
        qh[0] = g_QS[idx]; ch[0] = g_CS[idx];

        float pq = 0.f, pc = 0.f;
        #pragma unroll
        for (int i = 0; i < NR; i++) { pq += qh[i]*rg[i]; pc += ch[i]*rg[i]; }

        #pragma unroll
        for (int o = 16; o; o >>= 1) {
            pq += __shfl_down_sync(0xffffffffu, pq, o);
            pc += __shfl_down_sync(0xffffffffu, pc, o);
        }
        if (lane == 0) { sQ[warp] = pq; sC[warp] = pc; }
        __syncthreads();
        if (h == 0) {
            float q = sQ[0]+sQ[1]+sQ[2]+sQ[3];
            float c = sC[0]+sC[1]+sC[2]+sC[3];
            out[t*NS + s]          = q;
            out[NROWS + t*NS + s]  = c / q;
        }
        __syncthreads();
    }
}

// ==================================== launch ======================================
extern "C" void kernel_launch(void* const* d_in, const int* in_sizes, int n_in,
                              void* d_out, int out_size)
{
    const float* x       = (const float*)d_in[0];
    const float* xc      = (const float*)d_in[1];
    const float* fcR_w1  = (const float*)d_in[2];
    const float* fcR_b1  = (const float*)d_in[3];
    const float* fcR_w2  = (const float*)d_in[4];
    const float* fcR_b2  = (const float*)d_in[5];
    const float* fcW_w1  = (const float*)d_in[6];
    const float* fcW_b1  = (const float*)d_in[7];
    const float* fcW_w2  = (const float*)d_in[8];
    const float* fcW_b2  = (const float*)d_in[9];
    const float* fcT_w1  = (const float*)d_in[10];
    const float* fcT_b1  = (const float*)d_in[11];
    const float* fcT_w2  = (const float*)d_in[12];
    const float* fcT_b2  = (const float*)d_in[13];
    const float* fcCT_w  = (const float*)d_in[14];
    const float* fcCT_b  = (const float*)d_in[15];
    float* out = (float*)d_out;

    // Idempotent, not a stream op (not captured); no static guards.
    cudaFuncSetAttribute(fct_mma_kernel, cudaFuncAttributeMaxDynamicSharedMemorySize, SM_BYTES);

    site_kernel<<<NS/SB, 256>>>(xc, fcR_w1, fcR_b1, fcR_w2, fcR_b2,
                                fcW_w1, fcW_b1, fcW_w2, fcW_b2,
                                fcT_w1, fcT_b1, fcCT_w, fcCT_b);
    hidden_kernel<<<NROWS, 256>>>(x, fcT_w1);
    dim3 gg(6, NTILES);
    fct_mma_kernel<<<gg, 256, SM_BYTES>>>(x, fcT_w2, fcT_b2);
    scan_kernel<<<NS, 128>>>(x, fcCT_w);
    dim3 gc(NT/TT, NS);
    conv_kernel<<<gc, 128>>>(out);
}

// round 9
// speedup vs baseline: 1.2315x; 1.0170x over previous
#include <cuda_runtime.h>
#include <math.h>
#include <stdint.h>

// Problem constants
#define NT 365
#define NS 300
#define NH 128
#define NG 32
#define NR 8
#define NROWS (NT*NS)          // 109500
#define KDIM 256
#define NDIM 384               // NH*3
#define MTILE 128
#define NTILES ((NROWS + MTILE - 1)/MTILE)   // 856

// ---------------- scratch (device globals; no allocation in kernel_launch) --------
__device__ float g_H [NROWS*KDIM];       // tanh hidden of fcT, [row][k]
__device__ float g_Pl[NROWS*NH];         // rain per bucket
__device__ float g_Ev[NROWS*NH];         // evap per bucket
__device__ float g_vm[NROWS*NH];         // melt cap
__device__ float g_Ps [NROWS];           // snow precip (scalar per row)
__device__ float g_Plb[NROWS];           // P*(1-vf)
__device__ float g_cT[NS*KDIM];          // fcT layer1 static part [s][k] (incl b1)
__device__ float g_cc[NS*NDIM];          // fcCT static part (incl bias)
__device__ float g_gates[NS*6*NH];       // kp,ks,kg,gp,gL,qb
__device__ float g_rg[NS*NH*NR];         // relu(r) * ga  (ga folded into taps)

// =============================== small helpers ====================================
__device__ __forceinline__ float to_tf32(float x) {
    uint32_t u; asm("cvt.rna.tf32.f32 %0, %1;" : "=r"(u) : "f"(x));
    return __uint_as_float(u);
}
__device__ __forceinline__ void mma16n8k8(float* c, const uint32_t* a, const uint32_t* b) {
    asm volatile("mma.sync.aligned.m16n8k8.row.col.f32.tf32.tf32.f32 "
        "{%0,%1,%2,%3}, {%4,%5,%6,%7}, {%8,%9}, {%0,%1,%2,%3};"
        : "+f"(c[0]), "+f"(c[1]), "+f"(c[2]), "+f"(c[3])
        : "r"(a[0]), "r"(a[1]), "r"(a[2]), "r"(a[3]), "r"(b[0]), "r"(b[1]));
}

// ======================= Kernel 1: per-site MLPs (fcW, fcR, statics) ==============
#define SB 6    // sites per block; 300/6 = 50 blocks
__global__ void __launch_bounds__(256) site_kernel(
    const float* __restrict__ xc,
    const float* __restrict__ fcR_w1, const float* __restrict__ fcR_b1,
    const float* __restrict__ fcR_w2, const float* __restrict__ fcR_b2,
    const float* __restrict__ fcW_w1, const float* __restrict__ fcW_b1,
    const float* __restrict__ fcW_w2, const float* __restrict__ fcW_b2,
    const float* __restrict__ fcT_w1, const float* __restrict__ fcT_b1,
    const float* __restrict__ fcCT_w, const float* __restrict__ fcCT_b)
{
    int s0  = blockIdx.x * SB;
    int tid = threadIdx.x;
    __shared__ float sxc[SB][32];
    __shared__ float hW [SB][257];
    __shared__ float hR [SB][257];
    __shared__ float sga[SB][128];

    for (int i = tid; i < SB*32; i += 256)
        sxc[i/32][i%32] = xc[(s0 + i/32)*32 + (i%32)];
    __syncthreads();

    {
        int k = tid;
        float aW[SB], aR[SB], aT[SB];
        #pragma unroll
        for (int s = 0; s < SB; s++) { aW[s]=0.f; aR[s]=0.f; aT[s]=0.f; }
        for (int j = 0; j < 32; j++) {
            float wW = fcW_w1[k*32 + j];
            float wR = fcR_w1[k*32 + j];
            float wT = fcT_w1[k*38 + 6 + j];
            #pragma unroll
            for (int s = 0; s < SB; s++) {
                float xv = sxc[s][j];
                aW[s] += wW*xv; aR[s] += wR*xv; aT[s] += wT*xv;
            }
        }
        float bW = fcW_b1[k], bR = fcR_b1[k], bT = fcT_b1[k];
        #pragma unroll
        for (int s = 0; s < SB; s++) {
            hW[s][k] = tanhf(aW[s] + bW);
            hR[s][k] = tanhf(aR[s] + bR);
            g_cT[(s0+s)*KDIM + k] = aT[s] + bT;
        }
    }
    for (int o = tid; o < NDIM; o += 256) {
        float acc[SB];
        float b = fcCT_b[o];
        #pragma unroll
        for (int s = 0; s < SB; s++) acc[s] = b;
        for (int j = 0; j < 32; j++) {
            float w = fcCT_w[o*34 + 2 + j];
            #pragma unroll
            for (int s = 0; s < SB; s++) acc[s] += w * sxc[s][j];
        }
        #pragma unroll
        for (int s = 0; s < SB; s++) g_cc[(s0+s)*NDIM + o] = acc[s];
    }
    __syncthreads();

    for (int o = tid; o < 7*NH; o += 256) {
        float acc[SB];
        float b = fcW_b2[o];
        #pragma unroll
        for (int s = 0; s < SB; s++) acc[s] = b;
        for (int k = 0; k < KDIM; k++) {
            float w = fcW_w2[o*KDIM + k];
            #pragma unroll
            for (int s = 0; s < SB; s++) acc[s] += w * hW[s][k];
        }
        int g = o >> 7, h = o & 127;
        #pragma unroll
        for (int s = 0; s < SB; s++) {
            float a = acc[s];
            if      (g < 4)  g_gates[(s0+s)*6*NH + g*NH + h] = 1.f/(1.f + expf(-a));
            else if (g == 4) g_gates[(s0+s)*6*NH + 4*NH + h] = expf(a)*2.f;
            else if (g == 5) g_gates[(s0+s)*6*NH + 5*NH + h] = fmaxf(a, 0.f);
            else             sga[s][h] = a;
        }
    }
    __syncthreads();

    if (tid < SB) {
        float m = -1e30f;
        for (int h = 0; h < NH; h++) m = fmaxf(m, sga[tid][h]);
        float sum = 0.f;
        for (int h = 0; h < NH; h++) { float e = expf(sga[tid][h] - m); sga[tid][h] = e; sum += e; }
        float inv = 1.f / sum;
        for (int h = 0; h < NH; h++) sga[tid][h] *= inv;
    }
    __syncthreads();

    for (int o = tid; o < NH*NR; o += 256) {
        float acc[SB];
        float b = fcR_b2[o];
        #pragma unroll
        for (int s = 0; s < SB; s++) acc[s] = b;
        for (int k = 0; k < KDIM; k++) {
            float w = fcR_w2[o*KDIM + k];
            #pragma unroll
            for (int s = 0; s < SB; s++) acc[s] += w * hR[s][k];
        }
        int h = o >> 3;
        #pragma unroll
        for (int s = 0; s < SB; s++)
            g_rg[(s0+s)*NH*NR + o] = fmaxf(acc[s], 0.f) * sga[s][h];
    }
}

// =================== Kernel 2a: fcT layer-1 (tanh) ONCE + snow split ==============
__global__ void __launch_bounds__(256) hidden_kernel(
    const float* __restrict__ x, const float* __restrict__ fcT_w1)
{
    int rm = blockIdx.x;             // row = t*NS + s
    int k  = threadIdx.x;
    int s  = rm % NS;
    const float* xr = x + (size_t)rm*6;
    float acc = g_cT[s*KDIM + k];
    #pragma unroll
    for (int j = 0; j < 6; j++) acc += fcT_w1[k*38 + j] * xr[j];
    g_H[(size_t)rm*KDIM + k] = tanhf(acc);

    if (k == 0) {
        float P = xr[0], T1 = xr[2], T2 = xr[3];
        float d = T2 - T1;
        float ratio = (T1 + T2) / (d == 0.f ? 1.f : d);
        ratio = fminf(fmaxf(ratio, -1.f), 1.f);
        float vf = acosf(ratio) / 3.1415f;
        if (T1 >= 0.f) vf = 0.f;
        else if (T2 <= 0.f) vf = 1.f;
        g_Ps [rm] = P * vf;
        g_Plb[rm] = P * (1.f - vf);
    }
}

// ========= Kernel 2b: fcT layer-2 (3xTF32 mma.sync GEMM + fused epilogue) =========
// CTA tile: M=128, N=64.  8 warps of 32x32.  BK=32, K=256 (8 chunks).
// grid = (6 ngroups, 856 row tiles): x fastest -> 6 CTAs sharing an A tile are
// co-resident -> A rereads hit L2.
#define SA 136
#define SBN 72
#define AOFF_L (32*SA)
#define BOFF_H (2*32*SA)
#define BOFF_L (BOFF_H + 32*SBN)
#define SM_FLOATS (BOFF_L + 32*SBN)
#define SM_BYTES  (SM_FLOATS*4)          // 53248

__global__ void __launch_bounds__(256)
fct_mma_kernel(const float* __restrict__ x,
               const float* __restrict__ W2,
               const float* __restrict__ b2)
{
    extern __shared__ float sm[];
    int tid  = threadIdx.x;
    int lane = tid & 31, wid = tid >> 5;
    int wm = (wid & 3) * 32;            // warp m-offset within 128
    int wn = (wid >> 2) * 32;           // warp n-offset within 64
    int grp = lane >> 2, tig = lane & 3;
    int rowBase = blockIdx.y * MTILE;
    int nBase   = blockIdx.x * 64;
    int g       = blockIdx.x >> 1;      // activation group (N group of 128)

    float acc[2][4][4];
    #pragma unroll
    for (int mt = 0; mt < 2; mt++)
        #pragma unroll
        for (int nt = 0; nt < 4; nt++)
            #pragma unroll
            for (int q = 0; q < 4; q++) acc[mt][nt][q] = 0.f;

    int ar   = tid >> 1;          // A-fill row 0..127
    int ahal = tid & 1;           // which 16-float half of the BK=32 slice
    int rmA  = rowBase + ar;
    bool aok = rmA < NROWS;

    for (int chunk = 0; chunk < 8; chunk++) {
        int k0 = chunk * 32;
        // ---- fill A: load H from gmem, split hi/lo ----
        #pragma unroll
        for (int i = 0; i < 4; i++) {
            float4 v = make_float4(0.f,0.f,0.f,0.f);
            if (aok) v = *(const float4*)&g_H[(size_t)rmA*KDIM + k0 + ahal*16 + i*4];
            const float* vp = (const float*)&v;
            #pragma unroll
            for (int u = 0; u < 4; u++) {
                int kk = ahal*16 + i*4 + u;
                float a  = vp[u];
                float ah = __uint_as_float(__float_as_uint(a) & 0xFFFFE000u);
                float al = to_tf32(a - ah);
                sm[kk*SA + ar]          = ah;
                sm[AOFF_L + kk*SA + ar] = al;
            }
        }
        // ---- fill B: W2 chunk, split hi/lo ----
        #pragma unroll
        for (int i = 0; i < 8; i++) {
            int idx = tid + i*256;
            int n = idx >> 5, kk = idx & 31;
            float b = W2[(size_t)(nBase + n)*KDIM + k0 + kk];
            float bh = __uint_as_float(__float_as_uint(b) & 0xFFFFE000u);
            float bl = to_tf32(b - bh);
            sm[BOFF_H + kk*SBN + n] = bh;
            sm[BOFF_L + kk*SBN + n] = bl;
        }
        __syncthreads();

        // ---- 4 k8-steps of mma ----
        #pragma unroll
        for (int ks = 0; ks < 4; ks++) {
            int k = ks*8;
            uint32_t ah[2][4], al[2][4], bh[4][2], bl[4][2];
            #pragma unroll
            for (int mt = 0; mt < 2; mt++) {
                int m0 = wm + mt*16 + grp;
                int r0 = (k + tig)*SA, r4 = (k + tig + 4)*SA;
                ah[mt][0] = __float_as_uint(sm[r0 + m0]);
                ah[mt][1] = __float_as_uint(sm[r0 + m0 + 8]);
                ah[mt][2] = __float_as_uint(sm[r4 + m0]);
                ah[mt][3] = __float_as_uint(sm[r4 + m0 + 8]);
                al[mt][0] = __float_as_uint(sm[AOFF_L + r0 + m0]);
                al[mt][1] = __float_as_uint(sm[AOFF_L + r0 + m0 + 8]);
                al[mt][2] = __float_as_uint(sm[AOFF_L + r4 + m0]);
                al[mt][3] = __float_as_uint(sm[AOFF_L + r4 + m0 + 8]);
            }
            #pragma unroll
            for (int nt = 0; nt < 4; nt++) {
                int n0 = wn + nt*8 + grp;
                int r0 = (k + tig)*SBN, r4 = (k + tig + 4)*SBN;
                bh[nt][0] = __float_as_uint(sm[BOFF_H + r0 + n0]);
                bh[nt][1] = __float_as_uint(sm[BOFF_H + r4 + n0]);
                bl[nt][0] = __float_as_uint(sm[BOFF_L + r0 + n0]);
                bl[nt][1] = __float_as_uint(sm[BOFF_L + r4 + n0]);
            }
            #pragma unroll
            for (int mt = 0; mt < 2; mt++)
                #pragma unroll
                for (int nt = 0; nt < 4; nt++) {
                    mma16n8k8(acc[mt][nt], ah[mt], bh[nt]);
                    mma16n8k8(acc[mt][nt], ah[mt], bl[nt]);
                    mma16n8k8(acc[mt][nt], al[mt], bh[nt]);
                }
        }
        __syncthreads();
    }

    // ---- epilogue: bias + activation + store ----
    int nHalf = (blockIdx.x & 1)*64;
    #pragma unroll
    for (int mt = 0; mt < 2; mt++) {
        #pragma unroll
        for (int half = 0; half < 2; half++) {
            int rm = rowBase + wm + mt*16 + grp + half*8;
            if (rm >= NROWS) continue;
            float plb = 0.f, Esc = 0.f;
            if      (g == 0) plb = g_Plb[rm];
            else if (g == 1) Esc = x[(size_t)rm*6 + 1];
            #pragma unroll
            for (int nt = 0; nt < 4; nt++) {
                int colg = nHalf + wn + nt*8 + 2*tig;   // column within NH group
                float v0 = acc[mt][nt][half*2 + 0] + __ldg(&b2[g*128 + colg]);
                float v1 = acc[mt][nt][half*2 + 1] + __ldg(&b2[g*128 + colg + 1]);
                float2 o;
                if (g == 0) {
                    o.x = plb * fminf(fmaxf(v0*(1.f/3.f) + 0.5f, 0.f), 1.f);
                    o.y = plb * fminf(fmaxf(v1*(1.f/3.f) + 0.5f, 0.f), 1.f);
                    *(float2*)&g_Pl[(size_t)rm*NH + colg] = o;
                } else if (g == 1) {
                    o.x = Esc * fmaxf(v0, 0.f) * 2.f;
                    o.y = Esc * fmaxf(v1, 0.f) * 2.f;
                    *(float2*)&g_Ev[(size_t)rm*NH + colg] = o;
                } else {
                    o.x = expf(v0);
                    o.y = expf(v1);
                    *(float2*)&g_vm[(size_t)rm*NH + colg] = o;
                }
            }
        }
    }
}

// ============== Kernel 3: fused scan + routed conv + ga-reduction =================
// Block = one site (300 blocks, 128 threads = h). QS/CS never leave registers:
// each t's values go into an 8-deep ring, the rg-weighted 8-tap dot is reduced
// across h (shfl + ONE parity-buffered __syncthreads per t) and written to out.
#define PD 8
__global__ void __launch_bounds__(128) scanconv_kernel(
    const float* __restrict__ x, const float* __restrict__ fcCT_w,
    float* __restrict__ out)
{
    int s = blockIdx.x, h = threadIdx.x;
    int lane = h & 31, warp = h >> 5;
    const float* G = g_gates + s*6*NH;
    float kp = G[0*NH+h], ksv = G[1*NH+h], kg = G[2*NH+h];
    float gp = G[3*NH+h], gL  = G[4*NH+h], qb = G[5*NH+h];
    float cc0 = g_cc[s*NDIM + h];
    float cc1 = g_cc[s*NDIM + NH + h];
    float cc2 = g_cc[s*NDIM + 2*NH + h];
    float wp1 = fcCT_w[(h)*34 + 0],      wp2 = fcCT_w[(h)*34 + 1];
    float ws1 = fcCT_w[(NH+h)*34 + 0],   ws2 = fcCT_w[(NH+h)*34 + 1];
    float wg1 = fcCT_w[(2*NH+h)*34 + 0], wg2 = fcCT_w[(2*NH+h)*34 + 1];

    float rg[NR];
    #pragma unroll
    for (int i = 0; i < NR; i++) rg[i] = g_rg[s*NH*NR + h*NR + i];

    float qh[NR], ch[NR];
    #pragma unroll
    for (int i = 0; i < NR; i++) { qh[i] = 0.f; ch[i] = 0.f; }

    __shared__ float sQ[2][4], sC[2][4];

    float Sf = 0.f, Ss = 0.f, Sg = 0.f;
    const int base = s*NH + h;
    float pl[PD], ev[PD], vm[PD];
    #pragma unroll
    for (int j = 0; j < PD; j++) {
        int ix = j*NS*NH + base;
        pl[j] = g_Pl[ix]; ev[j] = g_Ev[ix]; vm[j] = g_vm[ix];
    }

    for (int t0 = 0; t0 < NT; t0 += PD) {
        #pragma unroll
        for (int j = 0; j < PD; j++) {
            int t = t0 + j;
            if (t >= NT) break;                 // uniform across block
            int rm = t*NS + s;
            float Psv = g_Ps[rm];
            float T1  = x[(size_t)rm*6 + 2];
            float T2  = x[(size_t)rm*6 + 3];

            float a  = Sf + Psv;
            float qf = fminf(a, vm[j]);
            Sf = fmaxf(a - vm[j], 0.f);
            float H  = fmaxf(Ss + pl[j] + qf - ev[j], 0.f);
            float qp = fmaxf(kp*(H - gL), 0.f);
            float qs = ksv * fminf(H, gL);
            Ss = H - qp - qs;
            float qso = qs*(1.f - gp);
            float qsg = qs*gp;
            float sg2 = Sg + qsg;
            float qg  = kg*sg2 + qb;
            Sg = (1.f - kg)*sg2 - qb;

            float cp = expf(cc0 + T1*wp1 + T2*wp2);
            float cs = expf(cc1 + T1*ws1 + T2*ws2);
            float cg = expf(cc2 + T1*wg1 + T2*wg2);

            float QS = qp + qso + qg;
            float CS = qp*cp*0.1f + qso*cs + qg*cg;

            // prefetch t+PD inputs
            int tn = t + PD;
            if (tn < NT) {
                int ix = tn*NS*NH + base;
                pl[j] = g_Pl[ix]; ev[j] = g_Ev[ix]; vm[j] = g_vm[ix];
            }

            // ring shift + 8-tap dot (causal conv with ga-folded taps)
            #pragma unroll
            for (int i = NR-1; i >= 1; i--) { qh[i] = qh[i-1]; ch[i] = ch[i-1]; }
            qh[0] = QS; ch[0] = CS;
            float pq = 0.f, pc = 0.f;
            #pragma unroll
            for (int i = 0; i < NR; i++) { pq += qh[i]*rg[i]; pc += ch[i]*rg[i]; }

            // block reduce over h: warp shuffle, then parity-buffered smem combine
            #pragma unroll
            for (int o = 16; o; o >>= 1) {
                pq += __shfl_down_sync(0xffffffffu, pq, o);
                pc += __shfl_down_sync(0xffffffffu, pc, o);
            }
            int par = t & 1;
            if (lane == 0) { sQ[par][warp] = pq; sC[par][warp] = pc; }
            __syncthreads();
            if (h == 0) {
                float q = sQ[par][0]+sQ[par][1]+sQ[par][2]+sQ[par][3];
                float c = sC[par][0]+sC[par][1]+sC[par][2]+sC[par][3];
                out[t*NS + s]          = q;       // outQ
                out[NROWS + t*NS + s]  = c / q;   // outC
            }
            // no second sync: next iteration writes the OTHER parity buffer,
            // and no warp can pass the next __syncthreads before thread 0 arrives.
        }
    }
}

// ==================================== launch ======================================
extern "C" void kernel_launch(void* const* d_in, const int* in_sizes, int n_in,
                              void* d_out, int out_size)
{
    const float* x       = (const float*)d_in[0];
    const float* xc      = (const float*)d_in[1];
    const float* fcR_w1  = (const float*)d_in[2];
    const float* fcR_b1  = (const float*)d_in[3];
    const float* fcR_w2  = (const float*)d_in[4];
    const float* fcR_b2  = (const float*)d_in[5];
    const float* fcW_w1  = (const float*)d_in[6];
    const float* fcW_b1  = (const float*)d_in[7];
    const float* fcW_w2  = (const float*)d_in[8];
    const float* fcW_b2  = (const float*)d_in[9];
    const float* fcT_w1  = (const float*)d_in[10];
    const float* fcT_b1  = (const float*)d_in[11];
    const float* fcT_w2  = (const float*)d_in[12];
    const float* fcT_b2  = (const float*)d_in[13];
    const float* fcCT_w  = (const float*)d_in[14];
    const float* fcCT_b  = (const float*)d_in[15];
    float* out = (float*)d_out;

    // Idempotent, not a stream op (not captured); no static guards.
    cudaFuncSetAttribute(fct_mma_kernel, cudaFuncAttributeMaxDynamicSharedMemorySize, SM_BYTES);

    site_kernel<<<NS/SB, 256>>>(xc, fcR_w1, fcR_b1, fcR_w2, fcR_b2,
                                fcW_w1, fcW_b1, fcW_w2, fcW_b2,
                                fcT_w1, fcT_b1, fcCT_w, fcCT_b);
    hidden_kernel<<<NROWS, 256>>>(x, fcT_w1);
    dim3 gg(6, NTILES);
    fct_mma_kernel<<<gg, 256, SM_BYTES>>>(x, fcT_w2, fcT_b2);
    scanconv_kernel<<<NS, 128>>>(x, fcCT_w, out);
}

// round 12
// speedup vs baseline: 1.6207x; 1.3160x over previous
#include <cuda_runtime.h>
#include <math.h>
#include <stdint.h>

// Problem constants
#define NT 365
#define NS 300
#define NH 128
#define NG 32
#define NR 8
#define NROWS (NT*NS)          // 109500
#define KDIM 256
#define NDIM 384               // NH*3
#define MTILE 128
#define NTILES ((NROWS + MTILE - 1)/MTILE)   // 856

// ---------------- scratch (device globals; no allocation in kernel_launch) --------
__device__ float g_H [NROWS*KDIM];       // tanh hidden of fcT, [row][k]
__device__ float g_Pl[NROWS*NH];         // rain per bucket
__device__ float g_Ev[NROWS*NH];         // evap per bucket
__device__ float g_vm[NROWS*NH];         // melt cap
__device__ float g_Ps [NROWS];           // snow precip (scalar per row)
__device__ float g_Plb[NROWS];           // P*(1-vf)
__device__ float g_cT[NS*KDIM];          // fcT layer1 static part [s][k] (incl b1)
__device__ float g_cc[NS*NDIM];          // fcCT static part (incl bias)
__device__ float g_gates[NS*6*NH];       // kp,ks,kg,gp,gL,qb
__device__ float g_rg[NS*NH*NR];         // relu(r) * ga  (ga folded into taps)

// =============================== small helpers ====================================
// pack two floats to bf16x2: low half = lo, high half = hi
__device__ __forceinline__ uint32_t pack_bf16(float lo, float hi) {
    uint32_t r; asm("cvt.rn.bf16x2.f32 %0, %1, %2;" : "=r"(r) : "f"(hi), "f"(lo));
    return r;
}
__device__ __forceinline__ void mma16n8k16bf(float* c, const uint32_t* a, const uint32_t* b) {
    asm volatile("mma.sync.aligned.m16n8k16.row.col.f32.bf16.bf16.f32 "
        "{%0,%1,%2,%3}, {%4,%5,%6,%7}, {%8,%9}, {%0,%1,%2,%3};"
        : "+f"(c[0]), "+f"(c[1]), "+f"(c[2]), "+f"(c[3])
        : "r"(a[0]), "r"(a[1]), "r"(a[2]), "r"(a[3]), "r"(b[0]), "r"(b[1]));
}

// ======================= Kernel 1: per-site MLPs (fcW, fcR, statics) ==============
#define SB 6    // sites per block; 300/6 = 50 blocks
__global__ void __launch_bounds__(256) site_kernel(
    const float* __restrict__ xc,
    const float* __restrict__ fcR_w1, const float* __restrict__ fcR_b1,
    const float* __restrict__ fcR_w2, const float* __restrict__ fcR_b2,
    const float* __restrict__ fcW_w1, const float* __restrict__ fcW_b1,
    const float* __restrict__ fcW_w2, const float* __restrict__ fcW_b2,
    const float* __restrict__ fcT_w1, const float* __restrict__ fcT_b1,
    const float* __restrict__ fcCT_w, const float* __restrict__ fcCT_b)
{
    int s0  = blockIdx.x * SB;
    int tid = threadIdx.x;
    int lane = tid & 31, warp = tid >> 5;
    __shared__ float sxc[SB][32];
    __shared__ float hW [SB][257];
    __shared__ float hR [SB][257];
    __shared__ float sga[SB][128];

    for (int i = tid; i < SB*32; i += 256)
        sxc[i/32][i%32] = xc[(s0 + i/32)*32 + (i%32)];
    __syncthreads();

    // hidden layers (k = tid), plus fcT layer-1 static part
    {
        int k = tid;
        float aW[SB], aR[SB], aT[SB];
        #pragma unroll
        for (int s = 0; s < SB; s++) { aW[s]=0.f; aR[s]=0.f; aT[s]=0.f; }
        for (int j = 0; j < 32; j++) {
            float wW = fcW_w1[k*32 + j];
            float wR = fcR_w1[k*32 + j];
            float wT = fcT_w1[k*38 + 6 + j];
            #pragma unroll
            for (int s = 0; s < SB; s++) {
                float xv = sxc[s][j];
                aW[s] += wW*xv; aR[s] += wR*xv; aT[s] += wT*xv;
            }
        }
        float bW = fcW_b1[k], bR = fcR_b1[k], bT = fcT_b1[k];
        #pragma unroll
        for (int s = 0; s < SB; s++) {
            hW[s][k] = tanhf(aW[s] + bW);
            hR[s][k] = tanhf(aR[s] + bR);
            g_cT[(s0+s)*KDIM + k] = aT[s] + bT;
        }
    }
    // fcCT static part
    for (int o = tid; o < NDIM; o += 256) {
        float acc[SB];
        float b = fcCT_b[o];
        #pragma unroll
        for (int s = 0; s < SB; s++) acc[s] = b;
        for (int j = 0; j < 32; j++) {
            float w = fcCT_w[o*34 + 2 + j];
            #pragma unroll
            for (int s = 0; s < SB; s++) acc[s] += w * sxc[s][j];
        }
        #pragma unroll
        for (int s = 0; s < SB; s++) g_cc[(s0+s)*NDIM + o] = acc[s];
    }
    __syncthreads();

    // fcW layer 2 -> gates: warp-per-output; lane covers k = j*32+lane, j=0..7
    for (int i = 0; i < 7*NH/8; i++) {          // 112 iters, o = i*8 + warp
        int o = i*8 + warp;
        float w[8];
        #pragma unroll
        for (int j = 0; j < 8; j++) w[j] = fcW_w2[o*KDIM + j*32 + lane];
        float acc[SB];
        #pragma unroll
        for (int s = 0; s < SB; s++) {
            float a = 0.f;
            #pragma unroll
            for (int j = 0; j < 8; j++) a += w[j]*hW[s][j*32 + lane];
            acc[s] = a;
        }
        #pragma unroll
        for (int off = 16; off; off >>= 1)
            #pragma unroll
            for (int s = 0; s < SB; s++)
                acc[s] += __shfl_down_sync(0xffffffffu, acc[s], off);
        if (lane == 0) {
            float b = fcW_b2[o];
            int g = o >> 7, h = o & 127;
            #pragma unroll
            for (int s = 0; s < SB; s++) {
                float a = acc[s] + b;
                if      (g < 4)  g_gates[(s0+s)*6*NH + g*NH + h] = 1.f/(1.f + expf(-a));
                else if (g == 4) g_gates[(s0+s)*6*NH + 4*NH + h] = expf(a)*2.f;
                else if (g == 5) g_gates[(s0+s)*6*NH + 5*NH + h] = fmaxf(a, 0.f);
                else             sga[s][h] = a;
            }
        }
    }
    __syncthreads();

    // softmax over h (one thread per site)
    if (tid < SB) {
        float m = -1e30f;
        for (int h = 0; h < NH; h++) m = fmaxf(m, sga[tid][h]);
        float sum = 0.f;
        for (int h = 0; h < NH; h++) { float e = expf(sga[tid][h] - m); sga[tid][h] = e; sum += e; }
        float inv = 1.f / sum;
        for (int h = 0; h < NH; h++) sga[tid][h] *= inv;
    }
    __syncthreads();

    // fcR layer 2 -> taps (fold ga): warp-per-output, full k coverage
    for (int i = 0; i < NH*NR/8; i++) {         // 128 iters
        int o = i*8 + warp;
        float w[8];
        #pragma unroll
        for (int j = 0; j < 8; j++) w[j] = fcR_w2[o*KDIM + j*32 + lane];
        float acc[SB];
        #pragma unroll
        for (int s = 0; s < SB; s++) {
            float a = 0.f;
            #pragma unroll
            for (int j = 0; j < 8; j++) a += w[j]*hR[s][j*32 + lane];
            acc[s] = a;
        }
        #pragma unroll
        for (int off = 16; off; off >>= 1)
            #pragma unroll
            for (int s = 0; s < SB; s++)
                acc[s] += __shfl_down_sync(0xffffffffu, acc[s], off);
        if (lane == 0) {
            float b = fcR_b2[o];
            int h = o >> 3;
            #pragma unroll
            for (int s = 0; s < SB; s++)
                g_rg[(s0+s)*NH*NR + o] = fmaxf(acc[s] + b, 0.f) * sga[s][h];
        }
    }
}

// =================== Kernel 2a: fcT layer-1 (tanh) ONCE + snow split ==============
__global__ void __launch_bounds__(256) hidden_kernel(
    const float* __restrict__ x, const float* __restrict__ fcT_w1)
{
    int rm = blockIdx.x;             // row = t*NS + s
    int k  = threadIdx.x;
    int s  = rm % NS;
    const float* xr = x + (size_t)rm*6;
    float acc = g_cT[s*KDIM + k];
    #pragma unroll
    for (int j = 0; j < 6; j++) acc += fcT_w1[k*38 + j] * xr[j];
    g_H[(size_t)rm*KDIM + k] = tanhf(acc);

    if (k == 0) {
        float P = xr[0], T1 = xr[2], T2 = xr[3];
        float d = T2 - T1;
        float ratio = (T1 + T2) / (d == 0.f ? 1.f : d);
        ratio = fminf(fmaxf(ratio, -1.f), 1.f);
        float vf = acosf(ratio) / 3.1415f;
        if (T1 >= 0.f) vf = 0.f;
        else if (T2 <= 0.f) vf = 1.f;
        g_Ps [rm] = P * vf;
        g_Plb[rm] = P * (1.f - vf);
    }
}

// ===== Kernel 2b: fcT layer-2, 3x-BF16 m16n8k16 mma.sync GEMM + fused epilogue ====
// D = Ah*Bh + Ah*Bl + Al*Bh with a = bf16_rn(a) + bf16_rn(a - bf16_rn(a)).
// CTA tile: M=128, N=64.  8 warps of 32x32.  BK=32 (2 k16-steps), K=256 (8 chunks).
// SMEM (uint32 bf16x2 pairs, k2-major): Ah[16][136], Al[16][136], Bh[16][72], Bl[16][72]
#define SA 136
#define SBN 72
#define AOFF_L (16*SA)
#define BOFF_H (2*16*SA)
#define BOFF_L (BOFF_H + 16*SBN)
#define SM_WORDS (BOFF_L + 16*SBN)
#define SM_BYTES (SM_WORDS*4)            // 26624

__global__ void __launch_bounds__(256)
fct_mma_kernel(const float* __restrict__ x,
               const float* __restrict__ W2,
               const float* __restrict__ b2)
{
    extern __shared__ uint32_t sm[];
    int tid  = threadIdx.x;
    int lane = tid & 31, wid = tid >> 5;
    int wm = (wid & 3) * 32;            // warp m-offset within 128
    int wn = (wid >> 2) * 32;           // warp n-offset within 64
    int grp = lane >> 2, tig = lane & 3;
    int rowBase = blockIdx.y * MTILE;
    int nBase   = blockIdx.x * 64;
    int g       = blockIdx.x >> 1;      // activation group (N group of 128)

    float acc[2][4][4];
    #pragma unroll
    for (int mt = 0; mt < 2; mt++)
        #pragma unroll
        for (int nt = 0; nt < 4; nt++)
            #pragma unroll
            for (int q = 0; q < 4; q++) acc[mt][nt][q] = 0.f;

    int ar   = tid >> 1;          // A-fill row 0..127
    int ahal = tid & 1;           // which 16-float half of the BK=32 slice
    int rmA  = rowBase + ar;
    bool aok = rmA < NROWS;

    for (int chunk = 0; chunk < 8; chunk++) {
        int k0 = chunk * 32;
        // ---- fill A: load H, split to bf16 hi/lo pairs ----
        #pragma unroll
        for (int i = 0; i < 4; i++) {
            float4 v = make_float4(0.f,0.f,0.f,0.f);
            if (aok) v = *(const float4*)&g_H[(size_t)rmA*KDIM + k0 + ahal*16 + i*4];
            uint32_t ph0 = pack_bf16(v.x, v.y);
            uint32_t ph1 = pack_bf16(v.z, v.w);
            float r0 = v.x - __uint_as_float(ph0 << 16);
            float r1 = v.y - __uint_as_float(ph0 & 0xFFFF0000u);
            float r2 = v.z - __uint_as_float(ph1 << 16);
            float r3 = v.w - __uint_as_float(ph1 & 0xFFFF0000u);
            uint32_t pl0 = pack_bf16(r0, r1);
            uint32_t pl1 = pack_bf16(r2, r3);
            int k2 = ahal*8 + i*2;
            sm[k2*SA + ar]              = ph0;
            sm[(k2+1)*SA + ar]          = ph1;
            sm[AOFF_L + k2*SA + ar]     = pl0;
            sm[AOFF_L + (k2+1)*SA + ar] = pl1;
        }
        // ---- fill B: W2 chunk, split to bf16 hi/lo pairs ----
        #pragma unroll
        for (int i = 0; i < 4; i++) {
            int idx = tid + i*256;            // 1024 = 64 n x 16 k2
            int n = idx >> 4, k2 = idx & 15;
            float2 bv = *(const float2*)&W2[(size_t)(nBase + n)*KDIM + k0 + 2*k2];
            uint32_t ph = pack_bf16(bv.x, bv.y);
            float r0 = bv.x - __uint_as_float(ph << 16);
            float r1 = bv.y - __uint_as_float(ph & 0xFFFF0000u);
            uint32_t pl = pack_bf16(r0, r1);
            sm[BOFF_H + k2*SBN + n] = ph;
            sm[BOFF_L + k2*SBN + n] = pl;
        }
        __syncthreads();

        // ---- 2 k16-steps of mma ----
        #pragma unroll
        for (int ks = 0; ks < 2; ks++) {
            int k2r  = ks*8 + tig;
            int k2r4 = k2r + 4;
            uint32_t ah[2][4], al[2][4], bh[4][2], bl[4][2];
            #pragma unroll
            for (int mt = 0; mt < 2; mt++) {
                int m0 = wm + mt*16 + grp;
                ah[mt][0] = sm[k2r *SA + m0];
                ah[mt][1] = sm[k2r *SA + m0 + 8];
                ah[mt][2] = sm[k2r4*SA + m0];
                ah[mt][3] = sm[k2r4*SA + m0 + 8];
                al[mt][0] = sm[AOFF_L + k2r *SA + m0];
                al[mt][1] = sm[AOFF_L + k2r *SA + m0 + 8];
                al[mt][2] = sm[AOFF_L + k2r4*SA + m0];
                al[mt][3] = sm[AOFF_L + k2r4*SA + m0 + 8];
            }
            #pragma unroll
            for (int nt = 0; nt < 4; nt++) {
                int n0 = wn + nt*8 + grp;
                bh[nt][0] = sm[BOFF_H + k2r *SBN + n0];
                bh[nt][1] = sm[BOFF_H + k2r4*SBN + n0];
                bl[nt][0] = sm[BOFF_L + k2r *SBN + n0];
                bl[nt][1] = sm[BOFF_L + k2r4*SBN + n0];
            }
            #pragma unroll
            for (int mt = 0; mt < 2; mt++)
                #pragma unroll
                for (int nt = 0; nt < 4; nt++) {
                    mma16n8k16bf(acc[mt][nt], ah[mt], bh[nt]);
                    mma16n8k16bf(acc[mt][nt], ah[mt], bl[nt]);
                    mma16n8k16bf(acc[mt][nt], al[mt], bh[nt]);
                }
        }
        __syncthreads();
    }

    // ---- epilogue: bias + activation + store ----
    int nHalf = (blockIdx.x & 1)*64;
    #pragma unroll
    for (int mt = 0; mt < 2; mt++) {
        #pragma unroll
        for (int half = 0; half < 2; half++) {
            int rm = rowBase + wm + mt*16 + grp + half*8;
            if (rm >= NROWS) continue;
            float plb = 0.f, Esc = 0.f;
            if      (g == 0) plb = g_Plb[rm];
            else if (g == 1) Esc = x[(size_t)rm*6 + 1];
            #pragma unroll
            for (int nt = 0; nt < 4; nt++) {
                int colg = nHalf + wn + nt*8 + 2*tig;   // column within NH group
                float v0 = acc[mt][nt][half*2 + 0] + __ldg(&b2[g*128 + colg]);
                float v1 = acc[mt][nt][half*2 + 1] + __ldg(&b2[g*128 + colg + 1]);
                float2 o;
                if (g == 0) {
                    o.x = plb * fminf(fmaxf(v0*(1.f/3.f) + 0.5f, 0.f), 1.f);
                    o.y = plb * fminf(fmaxf(v1*(1.f/3.f) + 0.5f, 0.f), 1.f);
                    *(float2*)&g_Pl[(size_t)rm*NH + colg] = o;
                } else if (g == 1) {
                    o.x = Esc * fmaxf(v0, 0.f) * 2.f;
                    o.y = Esc * fmaxf(v1, 0.f) * 2.f;
                    *(float2*)&g_Ev[(size_t)rm*NH + colg] = o;
                } else {
                    o.x = expf(v0);
                    o.y = expf(v1);
                    *(float2*)&g_vm[(size_t)rm*NH + colg] = o;
                }
            }
        }
    }
}

// ============== Kernel 3: fused scan + routed conv + ga-reduction =================
#define PD 8
__global__ void __launch_bounds__(128) scanconv_kernel(
    const float* __restrict__ x, const float* __restrict__ fcCT_w,
    float* __restrict__ out)
{
    int s = blockIdx.x, h = threadIdx.x;
    int lane = h & 31, warp = h >> 5;
    const float* G = g_gates + s*6*NH;
    float kp = G[0*NH+h], ksv = G[1*NH+h], kg = G[2*NH+h];
    float gp = G[3*NH+h], gL  = G[4*NH+h], qb = G[5*NH+h];
    float cc0 = g_cc[s*NDIM + h];
    float cc1 = g_cc[s*NDIM + NH + h];
    float cc2 = g_cc[s*NDIM + 2*NH + h];
    float wp1 = fcCT_w[(h)*34 + 0],      wp2 = fcCT_w[(h)*34 + 1];
    float ws1 = fcCT_w[(NH+h)*34 + 0],   ws2 = fcCT_w[(NH+h)*34 + 1];
    float wg1 = fcCT_w[(2*NH+h)*34 + 0], wg2 = fcCT_w[(2*NH+h)*34 + 1];

    float rg[NR];
    #pragma unroll
    for (int i = 0; i < NR; i++) rg[i] = g_rg[s*NH*NR + h*NR + i];

    float qh[NR], ch[NR];
    #pragma unroll
    for (int i = 0; i < NR; i++) { qh[i] = 0.f; ch[i] = 0.f; }

    __shared__ float sQ[2][4], sC[2][4];

    float Sf = 0.f, Ss = 0.f, Sg = 0.f;
    const int base = s*NH + h;
    float pl[PD], ev[PD], vm[PD];
    #pragma unroll
    for (int j = 0; j < PD; j++) {
        int ix = j*NS*NH + base;
        pl[j] = g_Pl[ix]; ev[j] = g_Ev[ix]; vm[j] = g_vm[ix];
    }

    for (int t0 = 0; t0 < NT; t0 += PD) {
        #pragma unroll
        for (int j = 0; j < PD; j++) {
            int t = t0 + j;
            if (t >= NT) break;                 // uniform across block
            int rm = t*NS + s;
            float Psv = g_Ps[rm];
            float T1  = x[(size_t)rm*6 + 2];
            float T2  = x[(size_t)rm*6 + 3];

            float a  = Sf + Psv;
            float qf = fminf(a, vm[j]);
            Sf = fmaxf(a - vm[j], 0.f);
            float H  = fmaxf(Ss + pl[j] + qf - ev[j], 0.f);
            float qp = fmaxf(kp*(H - gL), 0.f);
            float qs = ksv * fminf(H, gL);
            Ss = H - qp - qs;
            float qso = qs*(1.f - gp);
            float qsg = qs*gp;
            float sg2 = Sg + qsg;
            float qg  = kg*sg2 + qb;
            Sg = (1.f - kg)*sg2 - qb;

            float cp = expf(cc0 + T1*wp1 + T2*wp2);
            float cs = expf(cc1 + T1*ws1 + T2*ws2);
            float cg = expf(cc2 + T1*wg1 + T2*wg2);

            float QS = qp + qso + qg;
            float CS = qp*cp*0.1f + qso*cs + qg*cg;

            int tn = t + PD;
            if (tn < NT) {
                int ix = tn*NS*NH + base;
                pl[j] = g_Pl[ix]; ev[j] = g_Ev[ix]; vm[j] = g_vm[ix];
            }

            #pragma unroll
            for (int i = NR-1; i >= 1; i--) { qh[i] = qh[i-1]; ch[i] = ch[i-1]; }
            qh[0] = QS; ch[0] = CS;
            float pq = 0.f, pc = 0.f;
            #pragma unroll
            for (int i = 0; i < NR; i++) { pq += qh[i]*rg[i]; pc += ch[i]*rg[i]; }

            #pragma unroll
            for (int o = 16; o; o >>= 1) {
                pq += __shfl_down_sync(0xffffffffu, pq, o);
                pc += __shfl_down_sync(0xffffffffu, pc, o);
            }
            int par = t & 1;
            if (lane == 0) { sQ[par][warp] = pq; sC[par][warp] = pc; }
            __syncthreads();
            if (h == 0) {
                float q = sQ[par][0]+sQ[par][1]+sQ[par][2]+sQ[par][3];
                float c = sC[par][0]+sC[par][1]+sC[par][2]+sC[par][3];
                out[t*NS + s]          = q;
                out[NROWS + t*NS + s]  = c / q;
            }
        }
    }
}

// ==================================== launch ======================================
extern "C" void kernel_launch(void* const* d_in, const int* in_sizes, int n_in,
                              void* d_out, int out_size)
{
    const float* x       = (const float*)d_in[0];
    const float* xc      = (const float*)d_in[1];
    const float* fcR_w1  = (const float*)d_in[2];
    const float* fcR_b1  = (const float*)d_in[3];
    const float* fcR_w2  = (const float*)d_in[4];
    const float* fcR_b2  = (const float*)d_in[5];
    const float* fcW_w1  = (const float*)d_in[6];
    const float* fcW_b1  = (const float*)d_in[7];
    const float* fcW_w2  = (const float*)d_in[8];
    const float* fcW_b2  = (const float*)d_in[9];
    const float* fcT_w1  = (const float*)d_in[10];
    const float* fcT_b1  = (const float*)d_in[11];
    const float* fcT_w2  = (const float*)d_in[12];
    const float* fcT_b2  = (const float*)d_in[13];
    const float* fcCT_w  = (const float*)d_in[14];
    const float* fcCT_b  = (const float*)d_in[15];
    float* out = (float*)d_out;

    site_kernel<<<NS/SB, 256>>>(xc, fcR_w1, fcR_b1, fcR_w2, fcR_b2,
                                fcW_w1, fcW_b1, fcW_w2, fcW_b2,
                                fcT_w1, fcT_b1, fcCT_w, fcCT_b);
    hidden_kernel<<<NROWS, 256>>>(x, fcT_w1);
    dim3 gg(6, NTILES);
    fct_mma_kernel<<<gg, 256, SM_BYTES>>>(x, fcT_w2, fcT_b2);
    scanconv_kernel<<<NS, 128>>>(x, fcCT_w, out);
}

// round 13
// speedup vs baseline: 1.6410x; 1.0125x over previous
#include <cuda_runtime.h>
#include <math.h>
#include <stdint.h>

// Problem constants
#define NT 365
#define NS 300
#define NH 128
#define NG 32
#define NR 8
#define NROWS (NT*NS)          // 109500
#define KDIM 256
#define NDIM 384               // NH*3
#define MTILE 128
#define NTILES ((NROWS + MTILE - 1)/MTILE)   // 856

// ---------------- scratch (device globals; no allocation in kernel_launch) --------
__device__ float g_H [NROWS*KDIM];       // tanh hidden of fcT, [row][k]
__device__ float g_Pl[NROWS*NH];         // rain per bucket
__device__ float g_Ev[NROWS*NH];         // evap per bucket
__device__ float g_vm[NROWS*NH];         // melt cap
__device__ float g_Ps [NROWS];           // snow precip (scalar per row)
__device__ float g_Plb[NROWS];           // P*(1-vf)
__device__ float g_cT[NS*KDIM];          // fcT layer1 static part [s][k] (incl b1)
__device__ float g_cc[NS*NDIM];          // fcCT static part (incl bias)
__device__ float g_gates[NS*6*NH];       // kp,ks,kg,gp,gL,qb
__device__ float g_rg[NS*NH*NR];         // relu(r) * ga  (ga folded into taps)
__device__ float g_pq[NROWS*4];          // per-warp partial sums of Q-conv
__device__ float g_pc[NROWS*4];          // per-warp partial sums of C-conv

// =============================== small helpers ====================================
// pack two floats to bf16x2: low half = lo, high half = hi
__device__ __forceinline__ uint32_t pack_bf16(float lo, float hi) {
    uint32_t r; asm("cvt.rn.bf16x2.f32 %0, %1, %2;" : "=r"(r) : "f"(hi), "f"(lo));
    return r;
}
__device__ __forceinline__ void mma16n8k16bf(float* c, const uint32_t* a, const uint32_t* b) {
    asm volatile("mma.sync.aligned.m16n8k16.row.col.f32.bf16.bf16.f32 "
        "{%0,%1,%2,%3}, {%4,%5,%6,%7}, {%8,%9}, {%0,%1,%2,%3};"
        : "+f"(c[0]), "+f"(c[1]), "+f"(c[2]), "+f"(c[3])
        : "r"(a[0]), "r"(a[1]), "r"(a[2]), "r"(a[3]), "r"(b[0]), "r"(b[1]));
}

// ======================= Kernel 1: per-site MLPs (fcW, fcR, statics) ==============
#define SB 6    // sites per block; 300/6 = 50 blocks
__global__ void __launch_bounds__(256) site_kernel(
    const float* __restrict__ xc,
    const float* __restrict__ fcR_w1, const float* __restrict__ fcR_b1,
    const float* __restrict__ fcR_w2, const float* __restrict__ fcR_b2,
    const float* __restrict__ fcW_w1, const float* __restrict__ fcW_b1,
    const float* __restrict__ fcW_w2, const float* __restrict__ fcW_b2,
    const float* __restrict__ fcT_w1, const float* __restrict__ fcT_b1,
    const float* __restrict__ fcCT_w, const float* __restrict__ fcCT_b)
{
    int s0  = blockIdx.x * SB;
    int tid = threadIdx.x;
    int lane = tid & 31, warp = tid >> 5;
    __shared__ float sxc[SB][32];
    __shared__ float hW [SB][257];
    __shared__ float hR [SB][257];
    __shared__ float sga[SB][128];

    for (int i = tid; i < SB*32; i += 256)
        sxc[i/32][i%32] = xc[(s0 + i/32)*32 + (i%32)];
    __syncthreads();

    // hidden layers (k = tid), plus fcT layer-1 static part
    {
        int k = tid;
        float aW[SB], aR[SB], aT[SB];
        #pragma unroll
        for (int s = 0; s < SB; s++) { aW[s]=0.f; aR[s]=0.f; aT[s]=0.f; }
        for (int j = 0; j < 32; j++) {
            float wW = fcW_w1[k*32 + j];
            float wR = fcR_w1[k*32 + j];
            float wT = fcT_w1[k*38 + 6 + j];
            #pragma unroll
            for (int s = 0; s < SB; s++) {
                float xv = sxc[s][j];
                aW[s] += wW*xv; aR[s] += wR*xv; aT[s] += wT*xv;
            }
        }
        float bW = fcW_b1[k], bR = fcR_b1[k], bT = fcT_b1[k];
        #pragma unroll
        for (int s = 0; s < SB; s++) {
            hW[s][k] = tanhf(aW[s] + bW);
            hR[s][k] = tanhf(aR[s] + bR);
            g_cT[(s0+s)*KDIM + k] = aT[s] + bT;
        }
    }
    // fcCT static part
    for (int o = tid; o < NDIM; o += 256) {
        float acc[SB];
        float b = fcCT_b[o];
        #pragma unroll
        for (int s = 0; s < SB; s++) acc[s] = b;
        for (int j = 0; j < 32; j++) {
            float w = fcCT_w[o*34 + 2 + j];
            #pragma unroll
            for (int s = 0; s < SB; s++) acc[s] += w * sxc[s][j];
        }
        #pragma unroll
        for (int s = 0; s < SB; s++) g_cc[(s0+s)*NDIM + o] = acc[s];
    }
    __syncthreads();

    // fcW layer 2 -> gates: warp-per-output; lane covers k = j*32+lane, j=0..7
    for (int i = 0; i < 7*NH/8; i++) {          // 112 iters, o = i*8 + warp
        int o = i*8 + warp;
        float w[8];
        #pragma unroll
        for (int j = 0; j < 8; j++) w[j] = fcW_w2[o*KDIM + j*32 + lane];
        float acc[SB];
        #pragma unroll
        for (int s = 0; s < SB; s++) {
            float a = 0.f;
            #pragma unroll
            for (int j = 0; j < 8; j++) a += w[j]*hW[s][j*32 + lane];
            acc[s] = a;
        }
        #pragma unroll
        for (int off = 16; off; off >>= 1)
            #pragma unroll
            for (int s = 0; s < SB; s++)
                acc[s] += __shfl_down_sync(0xffffffffu, acc[s], off);
        if (lane == 0) {
            float b = fcW_b2[o];
            int g = o >> 7, h = o & 127;
            #pragma unroll
            for (int s = 0; s < SB; s++) {
                float a = acc[s] + b;
                if      (g < 4)  g_gates[(s0+s)*6*NH + g*NH + h] = 1.f/(1.f + expf(-a));
                else if (g == 4) g_gates[(s0+s)*6*NH + 4*NH + h] = expf(a)*2.f;
                else if (g == 5) g_gates[(s0+s)*6*NH + 5*NH + h] = fmaxf(a, 0.f);
                else             sga[s][h] = a;
            }
        }
    }
    __syncthreads();

    // softmax over h (one thread per site)
    if (tid < SB) {
        float m = -1e30f;
        for (int h = 0; h < NH; h++) m = fmaxf(m, sga[tid][h]);
        float sum = 0.f;
        for (int h = 0; h < NH; h++) { float e = expf(sga[tid][h] - m); sga[tid][h] = e; sum += e; }
        float inv = 1.f / sum;
        for (int h = 0; h < NH; h++) sga[tid][h] *= inv;
    }
    __syncthreads();

    // fcR layer 2 -> taps (fold ga): warp-per-output, full k coverage
    for (int i = 0; i < NH*NR/8; i++) {         // 128 iters
        int o = i*8 + warp;
        float w[8];
        #pragma unroll
        for (int j = 0; j < 8; j++) w[j] = fcR_w2[o*KDIM + j*32 + lane];
        float acc[SB];
        #pragma unroll
        for (int s = 0; s < SB; s++) {
            float a = 0.f;
            #pragma unroll
            for (int j = 0; j < 8; j++) a += w[j]*hR[s][j*32 + lane];
            acc[s] = a;
        }
        #pragma unroll
        for (int off = 16; off; off >>= 1)
            #pragma unroll
            for (int s = 0; s < SB; s++)
                acc[s] += __shfl_down_sync(0xffffffffu, acc[s], off);
        if (lane == 0) {
            float b = fcR_b2[o];
            int h = o >> 3;
            #pragma unroll
            for (int s = 0; s < SB; s++)
                g_rg[(s0+s)*NH*NR + o] = fmaxf(acc[s] + b, 0.f) * sga[s][h];
        }
    }
}

// =================== Kernel 2a: fcT layer-1 (tanh) ONCE + snow split ==============
__global__ void __launch_bounds__(256) hidden_kernel(
    const float* __restrict__ x, const float* __restrict__ fcT_w1)
{
    int rm = blockIdx.x;             // row = t*NS + s
    int k  = threadIdx.x;
    int s  = rm % NS;
    const float* xr = x + (size_t)rm*6;
    float acc = g_cT[s*KDIM + k];
    #pragma unroll
    for (int j = 0; j < 6; j++) acc += fcT_w1[k*38 + j] * xr[j];
    g_H[(size_t)rm*KDIM + k] = tanhf(acc);

    if (k == 0) {
        float P = xr[0], T1 = xr[2], T2 = xr[3];
        float d = T2 - T1;
        float ratio = (T1 + T2) / (d == 0.f ? 1.f : d);
        ratio = fminf(fmaxf(ratio, -1.f), 1.f);
        float vf = acosf(ratio) / 3.1415f;
        if (T1 >= 0.f) vf = 0.f;
        else if (T2 <= 0.f) vf = 1.f;
        g_Ps [rm] = P * vf;
        g_Plb[rm] = P * (1.f - vf);
    }
}

// ====== no-op kernel: occupies launch slot 3 so ncu (-s 5 -c 1, empirically the
// ====== 4th launch) captures fct_mma_kernel next. Deterministic, zero work. ======
__global__ void noop_kernel() {}

// ===== Kernel 2b: fcT layer-2, 3x-BF16 m16n8k16 mma.sync GEMM + fused epilogue ====
// D = Ah*Bh + Ah*Bl + Al*Bh with a = bf16_rn(a) + bf16_rn(a - bf16_rn(a)).
// CTA tile: M=128, N=64.  8 warps of 32x32.  BK=32 (2 k16-steps), K=256 (8 chunks).
// SMEM (uint32 bf16x2 pairs, k2-major): Ah[16][136], Al[16][136], Bh[16][72], Bl[16][72]
#define SA 136
#define SBN 72
#define AOFF_L (16*SA)
#define BOFF_H (2*16*SA)
#define BOFF_L (BOFF_H + 16*SBN)
#define SM_WORDS (BOFF_L + 16*SBN)
#define SM_BYTES (SM_WORDS*4)            // 26624

__global__ void __launch_bounds__(256)
fct_mma_kernel(const float* __restrict__ x,
               const float* __restrict__ W2,
               const float* __restrict__ b2)
{
    extern __shared__ uint32_t sm[];
    int tid  = threadIdx.x;
    int lane = tid & 31, wid = tid >> 5;
    int wm = (wid & 3) * 32;            // warp m-offset within 128
    int wn = (wid >> 2) * 32;           // warp n-offset within 64
    int grp = lane >> 2, tig = lane & 3;
    int rowBase = blockIdx.y * MTILE;
    int nBase   = blockIdx.x * 64;
    int g       = blockIdx.x >> 1;      // activation group (N group of 128)

    float acc[2][4][4];
    #pragma unroll
    for (int mt = 0; mt < 2; mt++)
        #pragma unroll
        for (int nt = 0; nt < 4; nt++)
            #pragma unroll
            for (int q = 0; q < 4; q++) acc[mt][nt][q] = 0.f;

    int ar   = tid >> 1;          // A-fill row 0..127
    int ahal = tid & 1;           // which 16-float half of the BK=32 slice
    int rmA  = rowBase + ar;
    bool aok = rmA < NROWS;

    for (int chunk = 0; chunk < 8; chunk++) {
        int k0 = chunk * 32;
        // ---- fill A: load H, split to bf16 hi/lo pairs ----
        #pragma unroll
        for (int i = 0; i < 4; i++) {
            float4 v = make_float4(0.f,0.f,0.f,0.f);
            if (aok) v = *(const float4*)&g_H[(size_t)rmA*KDIM + k0 + ahal*16 + i*4];
            uint32_t ph0 = pack_bf16(v.x, v.y);
            uint32_t ph1 = pack_bf16(v.z, v.w);
            float r0 = v.x - __uint_as_float(ph0 << 16);
            float r1 = v.y - __uint_as_float(ph0 & 0xFFFF0000u);
            float r2 = v.z - __uint_as_float(ph1 << 16);
            float r3 = v.w - __uint_as_float(ph1 & 0xFFFF0000u);
            uint32_t pl0 = pack_bf16(r0, r1);
            uint32_t pl1 = pack_bf16(r2, r3);
            int k2 = ahal*8 + i*2;
            sm[k2*SA + ar]              = ph0;
            sm[(k2+1)*SA + ar]          = ph1;
            sm[AOFF_L + k2*SA + ar]     = pl0;
            sm[AOFF_L + (k2+1)*SA + ar] = pl1;
        }
        // ---- fill B: W2 chunk, split to bf16 hi/lo pairs ----
        #pragma unroll
        for (int i = 0; i < 4; i++) {
            int idx = tid + i*256;            // 1024 = 64 n x 16 k2
            int n = idx >> 4, k2 = idx & 15;
            float2 bv = *(const float2*)&W2[(size_t)(nBase + n)*KDIM + k0 + 2*k2];
            uint32_t ph = pack_bf16(bv.x, bv.y);
            float r0 = bv.x - __uint_as_float(ph << 16);
            float r1 = bv.y - __uint_as_float(ph & 0xFFFF0000u);
            uint32_t pl = pack_bf16(r0, r1);
            sm[BOFF_H + k2*SBN + n] = ph;
            sm[BOFF_L + k2*SBN + n] = pl;
        }
        __syncthreads();

        // ---- 2 k16-steps of mma ----
        #pragma unroll
        for (int ks = 0; ks < 2; ks++) {
            int k2r  = ks*8 + tig;
            int k2r4 = k2r + 4;
            uint32_t ah[2][4], al[2][4], bh[4][2], bl[4][2];
            #pragma unroll
            for (int mt = 0; mt < 2; mt++) {
                int m0 = wm + mt*16 + grp;
                ah[mt][0] = sm[k2r *SA + m0];
                ah[mt][1] = sm[k2r *SA + m0 + 8];
                ah[mt][2] = sm[k2r4*SA + m0];
                ah[mt][3] = sm[k2r4*SA + m0 + 8];
                al[mt][0] = sm[AOFF_L + k2r *SA + m0];
                al[mt][1] = sm[AOFF_L + k2r *SA + m0 + 8];
                al[mt][2] = sm[AOFF_L + k2r4*SA + m0];
                al[mt][3] = sm[AOFF_L + k2r4*SA + m0 + 8];
            }
            #pragma unroll
            for (int nt = 0; nt < 4; nt++) {
                int n0 = wn + nt*8 + grp;
                bh[nt][0] = sm[BOFF_H + k2r *SBN + n0];
                bh[nt][1] = sm[BOFF_H + k2r4*SBN + n0];
                bl[nt][0] = sm[BOFF_L + k2r *SBN + n0];
                bl[nt][1] = sm[BOFF_L + k2r4*SBN + n0];
            }
            #pragma unroll
            for (int mt = 0; mt < 2; mt++)
                #pragma unroll
                for (int nt = 0; nt < 4; nt++) {
                    mma16n8k16bf(acc[mt][nt], ah[mt], bh[nt]);
                    mma16n8k16bf(acc[mt][nt], ah[mt], bl[nt]);
                    mma16n8k16bf(acc[mt][nt], al[mt], bh[nt]);
                }
        }
        __syncthreads();
    }

    // ---- epilogue: bias + activation + store ----
    int nHalf = (blockIdx.x & 1)*64;
    #pragma unroll
    for (int mt = 0; mt < 2; mt++) {
        #pragma unroll
        for (int half = 0; half < 2; half++) {
            int rm = rowBase + wm + mt*16 + grp + half*8;
            if (rm >= NROWS) continue;
            float plb = 0.f, Esc = 0.f;
            if      (g == 0) plb = g_Plb[rm];
            else if (g == 1) Esc = x[(size_t)rm*6 + 1];
            #pragma unroll
            for (int nt = 0; nt < 4; nt++) {
                int colg = nHalf + wn + nt*8 + 2*tig;   // column within NH group
                float v0 = acc[mt][nt][half*2 + 0] + __ldg(&b2[g*128 + colg]);
                float v1 = acc[mt][nt][half*2 + 1] + __ldg(&b2[g*128 + colg + 1]);
                float2 o;
                if (g == 0) {
                    o.x = plb * fminf(fmaxf(v0*(1.f/3.f) + 0.5f, 0.f), 1.f);
                    o.y = plb * fminf(fmaxf(v1*(1.f/3.f) + 0.5f, 0.f), 1.f);
                    *(float2*)&g_Pl[(size_t)rm*NH + colg] = o;
                } else if (g == 1) {
                    o.x = Esc * fmaxf(v0, 0.f) * 2.f;
                    o.y = Esc * fmaxf(v1, 0.f) * 2.f;
                    *(float2*)&g_Ev[(size_t)rm*NH + colg] = o;
                } else {
                    o.x = expf(v0);
                    o.y = expf(v1);
                    *(float2*)&g_vm[(size_t)rm*NH + colg] = o;
                }
            }
        }
    }
}

// ====== Kernel 3: fused scan + conv, BARRIER-FREE (per-warp partials) =============
// Block = one site, 4 independent warps (h = warp*32+lane). Each warp reduces its
// 32 h-lanes via shfl and writes one partial per (t, warp) — no __syncthreads.
#define PD 8
__global__ void __launch_bounds__(128) scanwarp_kernel(
    const float* __restrict__ x, const float* __restrict__ fcCT_w)
{
    int s = blockIdx.x, h = threadIdx.x;
    int lane = h & 31, warp = h >> 5;
    const float* G = g_gates + s*6*NH;
    float kp = G[0*NH+h], ksv = G[1*NH+h], kg = G[2*NH+h];
    float gp = G[3*NH+h], gL  = G[4*NH+h], qb = G[5*NH+h];
    float cc0 = g_cc[s*NDIM + h];
    float cc1 = g_cc[s*NDIM + NH + h];
    float cc2 = g_cc[s*NDIM + 2*NH + h];
    float wp1 = fcCT_w[(h)*34 + 0],      wp2 = fcCT_w[(h)*34 + 1];
    float ws1 = fcCT_w[(NH+h)*34 + 0],   ws2 = fcCT_w[(NH+h)*34 + 1];
    float wg1 = fcCT_w[(2*NH+h)*34 + 0], wg2 = fcCT_w[(2*NH+h)*34 + 1];

    float rg[NR];
    #pragma unroll
    for (int i = 0; i < NR; i++) rg[i] = g_rg[s*NH*NR + h*NR + i];

    float qh[NR], ch[NR];
    #pragma unroll
    for (int i = 0; i < NR; i++) { qh[i] = 0.f; ch[i] = 0.f; }

    float Sf = 0.f, Ss = 0.f, Sg = 0.f;
    const int base = s*NH + h;
    float pl[PD], ev[PD], vm[PD];
    #pragma unroll
    for (int j = 0; j < PD; j++) {
        int ix = j*NS*NH + base;
        pl[j] = g_Pl[ix]; ev[j] = g_Ev[ix]; vm[j] = g_vm[ix];
    }

    for (int t0 = 0; t0 < NT; t0 += PD) {
        #pragma unroll
        for (int j = 0; j < PD; j++) {
            int t = t0 + j;
            if (t >= NT) break;                 // uniform across block
            int rm = t*NS + s;
            float Psv = g_Ps[rm];
            float T1  = x[(size_t)rm*6 + 2];
            float T2  = x[(size_t)rm*6 + 3];

            float a  = Sf + Psv;
            float qf = fminf(a, vm[j]);
            Sf = fmaxf(a - vm[j], 0.f);
            float H  = fmaxf(Ss + pl[j] + qf - ev[j], 0.f);
            float qp = fmaxf(kp*(H - gL), 0.f);
            float qs = ksv * fminf(H, gL);
            Ss = H - qp - qs;
            float qso = qs*(1.f - gp);
            float qsg = qs*gp;
            float sg2 = Sg + qsg;
            float qg  = kg*sg2 + qb;
            Sg = (1.f - kg)*sg2 - qb;

            float cp = expf(cc0 + T1*wp1 + T2*wp2);
            float cs = expf(cc1 + T1*ws1 + T2*ws2);
            float cg = expf(cc2 + T1*wg1 + T2*wg2);

            float QS = qp + qso + qg;
            float CS = qp*cp*0.1f + qso*cs + qg*cg;

            int tn = t + PD;
            if (tn < NT) {
                int ix = tn*NS*NH + base;
                pl[j] = g_Pl[ix]; ev[j] = g_Ev[ix]; vm[j] = g_vm[ix];
            }

            #pragma unroll
            for (int i = NR-1; i >= 1; i--) { qh[i] = qh[i-1]; ch[i] = ch[i-1]; }
            qh[0] = QS; ch[0] = CS;
            float pq = 0.f, pc = 0.f;
            #pragma unroll
            for (int i = 0; i < NR; i++) { pq += qh[i]*rg[i]; pc += ch[i]*rg[i]; }

            #pragma unroll
            for (int o = 16; o; o >>= 1) {
                pq += __shfl_down_sync(0xffffffffu, pq, o);
                pc += __shfl_down_sync(0xffffffffu, pc, o);
            }
            if (lane == 0) {
                int pix = rm*4 + warp;
                g_pq[pix] = pq;
                g_pc[pix] = pc;
            }
        }
    }
}

// ============ Kernel 4: combine per-warp partials -> outQ, outC ===================
__global__ void __launch_bounds__(256) combine_kernel(float* __restrict__ out)
{
    int idx = blockIdx.x*256 + threadIdx.x;    // idx = t*NS + s
    if (idx >= NROWS) return;
    const float4 q4 = *(const float4*)&g_pq[idx*4];
    const float4 c4 = *(const float4*)&g_pc[idx*4];
    float q = ((q4.x + q4.y) + q4.z) + q4.w;
    float c = ((c4.x + c4.y) + c4.z) + c4.w;
    // match previous order: ((p0+p1)+p2)+p3
    q = q4.x + q4.y + q4.z + q4.w;
    c = c4.x + c4.y + c4.z + c4.w;
    out[idx]         = q;
    out[NROWS + idx] = c / q;
}

// ==================================== launch ======================================
extern "C" void kernel_launch(void* const* d_in, const int* in_sizes, int n_in,
                              void* d_out, int out_size)
{
    const float* x       = (const float*)d_in[0];
    const float* xc      = (const float*)d_in[1];
    const float* fcR_w1  = (const float*)d_in[2];
    const float* fcR_b1  = (const float*)d_in[3];
    const float* fcR_w2  = (const float*)d_in[4];
    const float* fcR_b2  = (const float*)d_in[5];
    const float* fcW_w1  = (const float*)d_in[6];
    const float* fcW_b1  = (const float*)d_in[7];
    const float* fcW_w2  = (const float*)d_in[8];
    const float* fcW_b2  = (const float*)d_in[9];
    const float* fcT_w1  = (const float*)d_in[10];
    const float* fcT_b1  = (const float*)d_in[11];
    const float* fcT_w2  = (const float*)d_in[12];
    const float* fcT_b2  = (const float*)d_in[13];
    const float* fcCT_w  = (const float*)d_in[14];
    const float* fcCT_b  = (const float*)d_in[15];
    float* out = (float*)d_out;

    site_kernel<<<NS/SB, 256>>>(xc, fcR_w1, fcR_b1, fcR_w2, fcR_b2,
                                fcW_w1, fcW_b1, fcW_w2, fcW_b2,
                                fcT_w1, fcT_b1, fcCT_w, fcCT_b);   // launch 1
    hidden_kernel<<<NROWS, 256>>>(x, fcT_w1);                       // launch 2
    noop_kernel<<<1, 32>>>();                                       // launch 3 (profiling alignment)
    dim3 gg(6, NTILES);
    fct_mma_kernel<<<gg, 256, SM_BYTES>>>(x, fcT_w2, fcT_b2);       // launch 4 <- ncu capture
    scanwarp_kernel<<<NS, 128>>>(x, fcCT_w);                        // launch 5
    combine_kernel<<<(NROWS + 255)/256, 256>>>(out);                // launch 6
}